// round 11
// baseline (speedup 1.0000x reference)
#include <cuda_runtime.h>
#include <cuda_fp16.h>
#include <cstdint>

#define BB   16384
#define DOBS 512
#define NE   8
#define NA   32
#define G1   256
#define G2   128
#define E1   1024
#define E2   512
#define E3   256
#define NP   (2*BB)

typedef __half h16;

// ---------------- scratch ----------------
__device__ __align__(16) h16 g_obs_h[BB*DOBS], g_obs_l[BB*DOBS];
__device__ __align__(16) h16 g_gw1h[DOBS*G1], g_gw1l[DOBS*G1];
__device__ __align__(16) h16 g_gw2h[G1*G2],   g_gw2l[G1*G2];
__device__ __align__(16) h16 g_ew1h[NE*DOBS*E1];
__device__ __align__(16) h16 g_ew2h[NE*E1*E2];
__device__ __align__(16) h16 g_ew3h[NE*E2*E3];

__device__ __align__(16) h16 g_g1h[BB*G1], g_g1l[BB*G1];
__device__ __align__(16) float g_g2[BB*G2];
// capacity-indexed expert activations: row = e*BB + slot
__device__ __align__(16) h16 g_h1[(size_t)NE*BB*E1];
__device__ __align__(16) h16 g_h2[(size_t)NE*BB*E2];
__device__ __align__(16) h16 g_h3[(size_t)NE*BB*E3];

__device__ int   g_cursor[NE];
__device__ int   g_tok[NE*BB];
__device__ float g_wt[NE*BB];

__device__ __forceinline__ float eluf(float x) { return x > 0.f ? x : expm1f(x); }

// ---------------- PTX helpers ----------------
__device__ __forceinline__ void mma_f16(float* c, const unsigned* a, const unsigned* b) {
    asm volatile(
        "mma.sync.aligned.m16n8k16.row.col.f32.f16.f16.f32 "
        "{%0,%1,%2,%3}, {%4,%5,%6,%7}, {%8,%9}, {%0,%1,%2,%3};"
        : "+f"(c[0]), "+f"(c[1]), "+f"(c[2]), "+f"(c[3])
        : "r"(a[0]), "r"(a[1]), "r"(a[2]), "r"(a[3]), "r"(b[0]), "r"(b[1]));
}
__device__ __forceinline__ void ldsm_x4(unsigned* r, unsigned addr) {
    asm volatile("ldmatrix.sync.aligned.m8n8.x4.shared.b16 {%0,%1,%2,%3}, [%4];"
                 : "=r"(r[0]), "=r"(r[1]), "=r"(r[2]), "=r"(r[3]) : "r"(addr));
}
__device__ __forceinline__ void ldsm_x4_t(unsigned* r, unsigned addr) {
    asm volatile("ldmatrix.sync.aligned.m8n8.x4.trans.shared.b16 {%0,%1,%2,%3}, [%4];"
                 : "=r"(r[0]), "=r"(r[1]), "=r"(r[2]), "=r"(r[3]) : "r"(addr));
}
__device__ __forceinline__ uint32_t s2u(const void* p) {
    uint32_t a;
    asm("{ .reg .u64 t; cvta.to.shared.u64 t, %1; cvt.u32.u64 %0, t; }" : "=r"(a) : "l"(p));
    return a;
}
__device__ __forceinline__ void cpa16(uint32_t dst, const void* src, uint32_t sz) {
    asm volatile("cp.async.cg.shared.global [%0], [%1], 16, %2;" :: "r"(dst), "l"(src), "r"(sz) : "memory");
}
__device__ __forceinline__ void cpcommit() { asm volatile("cp.async.commit_group;" ::: "memory"); }
template<int N> __device__ __forceinline__ void cpwait() { asm volatile("cp.async.wait_group %0;" :: "n"(N) : "memory"); }

// ---------------- fused split: all fp32->fp16(hi/lo) conversions in one launch ----------------
struct SplitArgs {
    const float4* x[6];
    __half2*      hi[6];
    __half2*      lo[6];     // null => hi only
    unsigned      end[6];    // cumulative n4
};

__global__ __launch_bounds__(256)
void split_all_kernel(SplitArgs a)
{
    unsigned i = blockIdx.x * 256 + threadIdx.x;
    if (blockIdx.x == 0 && threadIdx.x < NE) g_cursor[threadIdx.x] = 0;
    if (i >= a.end[5]) return;
    int s = 0;
    while (i >= a.end[s]) s++;
    unsigned base = s ? a.end[s-1] : 0;
    unsigned j = i - base;
    float4 v = a.x[s][j];
    h16 h0 = __float2half_rn(v.x), h1 = __float2half_rn(v.y);
    h16 h2 = __float2half_rn(v.z), h3 = __float2half_rn(v.w);
    a.hi[s][2*j]   = __halves2half2(h0, h1);
    a.hi[s][2*j+1] = __halves2half2(h2, h3);
    if (a.lo[s]) {
        a.lo[s][2*j]   = __halves2half2(__float2half_rn(v.x - __half2float(h0)),
                                        __float2half_rn(v.y - __half2float(h1)));
        a.lo[s][2*j+1] = __halves2half2(__float2half_rn(v.z - __half2float(h2)),
                                        __float2half_rn(v.w - __half2float(h3)));
    }
}

// ---------------- gating GEMM: 3-pass exact fp16 TC (128x128, BK=32, 3-stage) ----------------
#define A_BYTES 10240   // 128 x 40 halves
#define B_BYTES 8704    // 32 x 136 halves
#define SMEM3 (3 * (2*A_BYTES + 2*B_BYTES))   // 113664

template<int OUTM>   // 1 = fp16 hi/lo, 2 = fp32
__global__ __launch_bounds__(256)
void gate_gemm(const h16* __restrict__ Ah, const h16* __restrict__ Al,
               const h16* __restrict__ Wh, const h16* __restrict__ Wl,
               const float* __restrict__ bias,
               h16* __restrict__ Ch, h16* __restrict__ Cl, float* __restrict__ Cf,
               int K, int N)
{
    constexpr uint32_t AL_OFF = A_BYTES;
    constexpr uint32_t BH_OFF = 2*A_BYTES;
    constexpr uint32_t BL_OFF = BH_OFF + B_BYTES;
    constexpr uint32_t STG    = BH_OFF + 2*B_BYTES;

    extern __shared__ __align__(128) char sm[];
    const int row0 = blockIdx.x * 128;
    const int n0   = blockIdx.y * 128;
    const int tid = threadIdx.x, lane = tid & 31, wid = tid >> 5;
    const int warpM = wid & 3, warpN = wid >> 2;
    const uint32_t su = s2u(sm);

    const int ar  = tid >> 2;
    const int ach = tid & 3;
    const h16 *pAh[2], *pAl[2];
#pragma unroll
    for (int i = 0; i < 2; i++) {
        size_t rowIdx = (size_t)(row0 + ar + 64*i);
        pAh[i] = Ah + rowIdx * K + ach*8;
        pAl[i] = Al + rowIdx * K + ach*8;
    }
    const int br  = tid >> 4;
    const int bch = tid & 15;
    const h16* pBh = Wh + (size_t)br * N + n0 + bch*8;
    const h16* pBl = Wl + (size_t)br * N + n0 + bch*8;

    float acc[2][8][4];
#pragma unroll
    for (int mt = 0; mt < 2; mt++)
#pragma unroll
        for (int nt = 0; nt < 8; nt++)
#pragma unroll
            for (int q = 0; q < 4; q++) acc[mt][nt][q] = 0.f;

    const int S = K >> 5;

    auto LOAD = [&](int t) {
        uint32_t base = su + (uint32_t)(t % 3) * STG;
        int kf = t * 32;
#pragma unroll
        for (int i = 0; i < 2; i++) {
            uint32_t d = base + (uint32_t)((ar + 64*i)*80 + ach*16);
            cpa16(d, pAh[i] + kf, 16u);
            cpa16(d + AL_OFF, pAl[i] + kf, 16u);
        }
#pragma unroll
        for (int i = 0; i < 2; i++) {
            uint32_t d = base + (uint32_t)((br + 16*i)*272 + bch*16);
            cpa16(d + BH_OFF, pBh + (size_t)(kf + 16*i) * N, 16u);
            cpa16(d + BL_OFF, pBl + (size_t)(kf + 16*i) * N, 16u);
        }
        cpcommit();
    };

    LOAD(0);
    LOAD(1);

    for (int s = 0; s < S; s++) {
        __syncthreads();
        int rem = S - 1 - s;
        if (rem >= 2) { LOAD(s+2); cpwait<2>(); }
        else if (rem == 1) cpwait<1>();
        else cpwait<0>();
        __syncthreads();

        const uint32_t aBase = su + (uint32_t)(s % 3) * STG;
#pragma unroll
        for (int kk = 0; kk < 32; kk += 16) {
            unsigned ah[2][4], al[2][4];
#pragma unroll
            for (int mt = 0; mt < 2; mt++) {
                uint32_t off = (uint32_t)(((warpM*32 + mt*16 + (lane & 15))*40 + kk + 8*(lane >> 4)) * 2);
                ldsm_x4(ah[mt], aBase + off);
                ldsm_x4(al[mt], aBase + AL_OFF + off);
            }
            const int brow = kk + (lane & 15);
#pragma unroll
            for (int np = 0; np < 4; np++) {
                const int bcol = warpN*64 + np*16 + 8*(lane >> 4);
                uint32_t boff = (uint32_t)((brow*136 + bcol) * 2);
                unsigned bh[4], bl[4];
                ldsm_x4_t(bh, aBase + BH_OFF + boff);
                ldsm_x4_t(bl, aBase + BL_OFF + boff);
#pragma unroll
                for (int mt = 0; mt < 2; mt++) {
                    mma_f16(acc[mt][2*np],   ah[mt], bh);
                    mma_f16(acc[mt][2*np+1], ah[mt], bh+2);
                    mma_f16(acc[mt][2*np],   ah[mt], bl);
                    mma_f16(acc[mt][2*np+1], ah[mt], bl+2);
                    mma_f16(acc[mt][2*np],   al[mt], bh);
                    mma_f16(acc[mt][2*np+1], al[mt], bh+2);
                }
            }
        }
    }

#pragma unroll
    for (int mt = 0; mt < 2; mt++) {
        int r0 = row0 + warpM*32 + mt*16 + (lane >> 2);
#pragma unroll
        for (int nt = 0; nt < 8; nt++) {
            int c = n0 + warpN*64 + nt*8 + 2*(lane & 3);
            float b0 = __ldg(bias + c), b1 = __ldg(bias + c + 1);
            float v00 = eluf(acc[mt][nt][0] + b0);
            float v01 = eluf(acc[mt][nt][1] + b1);
            float v10 = eluf(acc[mt][nt][2] + b0);
            float v11 = eluf(acc[mt][nt][3] + b1);
#pragma unroll
            for (int rr = 0; rr < 2; rr++) {
                int r = r0 + rr*8;
                float va = rr ? v10 : v00, vb = rr ? v11 : v01;
                if (OUTM == 1) {
                    h16 h0 = __float2half_rn(va), h1 = __float2half_rn(vb);
                    *(__half2*)(Ch + (size_t)r*N + c) = __halves2half2(h0, h1);
                    *(__half2*)(Cl + (size_t)r*N + c) =
                        __halves2half2(__float2half_rn(va - __half2float(h0)),
                                       __float2half_rn(vb - __half2float(h1)));
                } else {
                    *(float2*)(Cf + (size_t)r*N + c) = make_float2(va, vb);
                }
            }
        }
    }
}

// ---------------- expert GEMM: 1-pass fp16, 128x128, BK=64, 2-stage double buffer ----------------
// capacity-region dispatch: blockIdx.x = e*128 + tile; rows e*BB .. e*BB+cnt[e]
#define XA_BYTES 18432   // 128 x 72 halves
#define XB_BYTES 17408   // 64 x 136 halves
#define XSTG     (XA_BYTES + XB_BYTES)   // 35840
#define SMEMX    (2*XSTG)                // 71680

template<bool GATHER>
__global__ __launch_bounds__(256)
void exp_gemm(const h16* __restrict__ A, const h16* __restrict__ W,
              const float* __restrict__ bias, h16* __restrict__ C,
              int K, int N)
{
    extern __shared__ __align__(128) char sm[];
    const int e   = blockIdx.x >> 7;
    const int t   = blockIdx.x & 127;
    const int cnt = g_cursor[e];
    if (t * 128 >= cnt) return;
    const int row0   = e*BB + t*128;
    const int rowEnd = e*BB + cnt;
    W    += (size_t)e * K * N;
    bias += e * N;

    const int n0  = blockIdx.y * 128;
    const int tid = threadIdx.x, lane = tid & 31, wid = tid >> 5;
    const int warpM = wid & 3, warpN = wid >> 2;
    const uint32_t su = s2u(sm);

    // A load: 1 row/thread pair: r = tid>>1 (0..127), hf = tid&1 covers 32-half half-row
    const int r  = tid >> 1;
    const int hf = tid & 1;
    const bool av = (row0 + r) < rowEnd;
    const uint32_t asz = av ? 16u : 0u;
    size_t rowIdx = 0;
    if (av) rowIdx = GATHER ? (size_t)g_tok[row0 + r] : (size_t)(row0 + r);
    const h16* pA = A + rowIdx * K + hf*32;
    // B load: br = tid>>2 (0..63), bq = tid&3 covers 32-half quarter-row
    const int br = tid >> 2;
    const int bq = tid & 3;
    const h16* pB = W + (size_t)br * N + n0 + bq*32;

    float acc[2][8][4];
#pragma unroll
    for (int mt = 0; mt < 2; mt++)
#pragma unroll
        for (int nt = 0; nt < 8; nt++)
#pragma unroll
            for (int q = 0; q < 4; q++) acc[mt][nt][q] = 0.f;

    const int S = K >> 6;

    auto LOAD = [&](int s) {
        uint32_t base = su + (uint32_t)(s & 1) * XSTG;
        int kf = s * 64;
        uint32_t da = base + (uint32_t)(r*144 + hf*64);
#pragma unroll
        for (int j = 0; j < 4; j++) cpa16(da + j*16, pA + kf + j*8, asz);
        uint32_t db = base + XA_BYTES + (uint32_t)(br*272 + bq*64);
#pragma unroll
        for (int j = 0; j < 4; j++) cpa16(db + j*16, pB + (size_t)kf * N + j*8, 16u);
        cpcommit();
    };

    LOAD(0);

    for (int s = 0; s < S; s++) {
        if (s + 1 < S) { LOAD(s+1); cpwait<1>(); }
        else cpwait<0>();
        __syncthreads();
        const uint32_t aBase = su + (uint32_t)(s & 1) * XSTG;
        const uint32_t bBase = aBase + XA_BYTES;
#pragma unroll
        for (int kk = 0; kk < 64; kk += 16) {
            unsigned ah[2][4];
#pragma unroll
            for (int mt = 0; mt < 2; mt++) {
                uint32_t off = (uint32_t)(((warpM*32 + mt*16 + (lane & 15))*72 + kk + 8*(lane >> 4)) * 2);
                ldsm_x4(ah[mt], aBase + off);
            }
            const int brow = kk + (lane & 15);
#pragma unroll
            for (int np = 0; np < 4; np++) {
                const int bcol = warpN*64 + np*16 + 8*(lane >> 4);
                unsigned bh[4];
                ldsm_x4_t(bh, bBase + (uint32_t)((brow*136 + bcol) * 2));
#pragma unroll
                for (int mt = 0; mt < 2; mt++) {
                    mma_f16(acc[mt][2*np],   ah[mt], bh);
                    mma_f16(acc[mt][2*np+1], ah[mt], bh+2);
                }
            }
        }
        __syncthreads();
    }

    // epilogue
#pragma unroll
    for (int mt = 0; mt < 2; mt++) {
        int r0 = row0 + warpM*32 + mt*16 + (lane >> 2);
#pragma unroll
        for (int nt = 0; nt < 8; nt++) {
            int c = n0 + warpN*64 + nt*8 + 2*(lane & 3);
            float b0 = __ldg(bias + c), b1 = __ldg(bias + c + 1);
            float v00 = eluf(acc[mt][nt][0] + b0);
            float v01 = eluf(acc[mt][nt][1] + b1);
            float v10 = eluf(acc[mt][nt][2] + b0);
            float v11 = eluf(acc[mt][nt][3] + b1);
#pragma unroll
            for (int rr = 0; rr < 2; rr++) {
                int rw = r0 + rr*8;
                float va = rr ? v10 : v00, vb = rr ? v11 : v01;
                if (rw < rowEnd)
                    *(__half2*)(C + (size_t)rw*N + c) =
                        __halves2half2(__float2half_rn(va), __float2half_rn(vb));
            }
        }
    }
}

// ---------------- fused gating head: logits + top-2 + renorm + direct scatter ----------------
__global__ __launch_bounds__(256)
void topk_scatter_kernel(const float* __restrict__ gw3, const float* __restrict__ gb3)
{
    __shared__ float sW[G2*NE];
    __shared__ float sB[NE];
    const int tid = threadIdx.x;
    const int lane = tid & 31;
    for (int i = tid; i < G2*NE; i += 256) sW[i] = gw3[i];
    if (tid < NE) sB[tid] = gb3[tid];
    __syncthreads();

    const int b = blockIdx.x * 256 + tid;
    const float4* g = (const float4*)(g_g2 + (size_t)b * G2);
    float lg[NE];
#pragma unroll
    for (int j = 0; j < NE; j++) lg[j] = sB[j];
#pragma unroll 4
    for (int k4 = 0; k4 < G2/4; k4++) {
        float4 v = g[k4];
        const float* w = sW + k4*4*NE;
#pragma unroll
        for (int j = 0; j < NE; j++)
            lg[j] += v.x*w[j] + v.y*w[NE+j] + v.z*w[2*NE+j] + v.w*w[3*NE+j];
    }
    int i0 = 0; float m0 = lg[0];
#pragma unroll
    for (int j = 1; j < NE; j++) if (lg[j] > m0) { m0 = lg[j]; i0 = j; }
    int i1 = -1; float m1 = -3.4e38f;
#pragma unroll
    for (int j = 0; j < NE; j++) if (j != i0 && lg[j] > m1) { m1 = lg[j]; i1 = j; }
    float e1  = expf(m1 - m0);
    float inv = 1.f / (1.f + e1);
    float wv[2] = { inv, e1 * inv };
    int   ev[2] = { i0, i1 };

    // warp-aggregated scatter into capacity regions
#pragma unroll
    for (int s = 0; s < 2; s++) {
        int   e = ev[s];
        float w = wv[s];
#pragma unroll
        for (int ee = 0; ee < NE; ee++) {
            unsigned m = __ballot_sync(0xffffffffu, e == ee);
            if (e == ee) {
                int rank   = __popc(m & ((1u << lane) - 1u));
                int leader = __ffs(m) - 1;
                int base = 0;
                if (lane == leader) base = atomicAdd(&g_cursor[ee], __popc(m));
                base = __shfl_sync(m, base, leader);
                int p = ee*BB + base + rank;
                g_tok[p] = b; g_wt[p] = w;
            }
        }
    }
}

// ---------------- layer 4 (K=256, N=32) + weighted combine, 128 rows/block ----------------
__global__ __launch_bounds__(256)
void l4_combine_kernel(const float* __restrict__ W4, const float* __restrict__ B4,
                       float* __restrict__ out)
{
    const int e   = blockIdx.x >> 7;
    const int t   = blockIdx.x & 127;
    const int cnt = g_cursor[e];
    if (t * 128 >= cnt) return;
    const int row0   = e*BB + t*128;
    const int rowEnd = e*BB + cnt;

    __shared__ float sW[E3*NA];
    const float* We = W4 + (size_t)e * E3 * NA;
    for (int i = threadIdx.x; i < E3*NA/4; i += 256)
        *(float4*)&sW[i*4] = *(const float4*)&We[i*4];
    __syncthreads();

    const int r  = threadIdx.x >> 3;
    const int c4 = (threadIdx.x & 7) * 4;
    const float bb0 = B4[e*NA + c4 + 0], bb1 = B4[e*NA + c4 + 1];
    const float bb2 = B4[e*NA + c4 + 2], bb3 = B4[e*NA + c4 + 3];

#pragma unroll
    for (int it = 0; it < 4; it++) {
        const int row = row0 + r + 32*it;
        if (row >= rowEnd) break;
        const __half2* hh = (const __half2*)(g_h3 + (size_t)row * E3);
        float a0 = 0.f, a1 = 0.f, a2 = 0.f, a3 = 0.f;
#pragma unroll 4
        for (int k = 0; k < E3; k += 4) {
            float2 p0 = __half22float2(hh[k/2]);
            float2 p1 = __half22float2(hh[k/2+1]);
            float4 w0 = *(float4*)&sW[(k+0)*NA + c4];
            float4 w1 = *(float4*)&sW[(k+1)*NA + c4];
            float4 w2 = *(float4*)&sW[(k+2)*NA + c4];
            float4 w3 = *(float4*)&sW[(k+3)*NA + c4];
            a0 += p0.x*w0.x + p0.y*w1.x + p1.x*w2.x + p1.y*w3.x;
            a1 += p0.x*w0.y + p0.y*w1.y + p1.x*w2.y + p1.y*w3.y;
            a2 += p0.x*w0.z + p0.y*w1.z + p1.x*w2.z + p1.y*w3.z;
            a3 += p0.x*w0.w + p0.y*w1.w + p1.x*w2.w + p1.y*w3.w;
        }
        const int   tok = g_tok[row];
        const float w   = g_wt[row];
        float* o = out + (size_t)tok * NA + c4;
        atomicAdd(o+0, w*(a0 + bb0));
        atomicAdd(o+1, w*(a1 + bb1));
        atomicAdd(o+2, w*(a2 + bb2));
        atomicAdd(o+3, w*(a3 + bb3));
    }
}

// ---------------- launch ----------------
extern "C" void kernel_launch(void* const* d_in, const int* in_sizes, int n_in,
                              void* d_out, int out_size)
{
    const float* obs = (const float*)d_in[0];
    const float* gw1 = (const float*)d_in[1];
    const float* gb1 = (const float*)d_in[2];
    const float* gw2 = (const float*)d_in[3];
    const float* gb2 = (const float*)d_in[4];
    const float* gw3 = (const float*)d_in[5];
    const float* gb3 = (const float*)d_in[6];
    const float* ew1 = (const float*)d_in[7];
    const float* eb1 = (const float*)d_in[8];
    const float* ew2 = (const float*)d_in[9];
    const float* eb2 = (const float*)d_in[10];
    const float* ew3 = (const float*)d_in[11];
    const float* eb3 = (const float*)d_in[12];
    const float* ew4 = (const float*)d_in[13];
    const float* eb4 = (const float*)d_in[14];
    float* out = (float*)d_out;

    h16 *obs_h, *obs_l, *gw1h, *gw1l, *gw2h, *gw2l;
    h16 *ew1h, *ew2h, *ew3h;
    h16 *g1h, *g1l, *h1, *h2, *h3;
    float *pg2;
    cudaGetSymbolAddress((void**)&obs_h, g_obs_h); cudaGetSymbolAddress((void**)&obs_l, g_obs_l);
    cudaGetSymbolAddress((void**)&gw1h, g_gw1h);   cudaGetSymbolAddress((void**)&gw1l, g_gw1l);
    cudaGetSymbolAddress((void**)&gw2h, g_gw2h);   cudaGetSymbolAddress((void**)&gw2l, g_gw2l);
    cudaGetSymbolAddress((void**)&ew1h, g_ew1h);
    cudaGetSymbolAddress((void**)&ew2h, g_ew2h);
    cudaGetSymbolAddress((void**)&ew3h, g_ew3h);
    cudaGetSymbolAddress((void**)&g1h, g_g1h);     cudaGetSymbolAddress((void**)&g1l, g_g1l);
    cudaGetSymbolAddress((void**)&h1, g_h1);
    cudaGetSymbolAddress((void**)&h2, g_h2);
    cudaGetSymbolAddress((void**)&h3, g_h3);
    cudaGetSymbolAddress((void**)&pg2, g_g2);

    cudaFuncSetAttribute(gate_gemm<1>,     cudaFuncAttributeMaxDynamicSharedMemorySize, SMEM3);
    cudaFuncSetAttribute(gate_gemm<2>,     cudaFuncAttributeMaxDynamicSharedMemorySize, SMEM3);
    cudaFuncSetAttribute(exp_gemm<true >,  cudaFuncAttributeMaxDynamicSharedMemorySize, SMEMX);
    cudaFuncSetAttribute(exp_gemm<false>,  cudaFuncAttributeMaxDynamicSharedMemorySize, SMEMX);

    // (1) fused splits (also zeroes expert cursors)
    SplitArgs sa;
    unsigned n0 = BB*DOBS/4, n1 = DOBS*G1/4, n2 = G1*G2/4;
    unsigned n3 = NE*DOBS*E1/4, n4 = NE*E1*E2/4, n5 = NE*E2*E3/4;
    sa.x[0]=(const float4*)obs; sa.hi[0]=(__half2*)obs_h; sa.lo[0]=(__half2*)obs_l;
    sa.x[1]=(const float4*)gw1; sa.hi[1]=(__half2*)gw1h;  sa.lo[1]=(__half2*)gw1l;
    sa.x[2]=(const float4*)gw2; sa.hi[2]=(__half2*)gw2h;  sa.lo[2]=(__half2*)gw2l;
    sa.x[3]=(const float4*)ew1; sa.hi[3]=(__half2*)ew1h;  sa.lo[3]=nullptr;
    sa.x[4]=(const float4*)ew2; sa.hi[4]=(__half2*)ew2h;  sa.lo[4]=nullptr;
    sa.x[5]=(const float4*)ew3; sa.hi[5]=(__half2*)ew3h;  sa.lo[5]=nullptr;
    sa.end[0]=n0; sa.end[1]=n0+n1; sa.end[2]=n0+n1+n2;
    sa.end[3]=sa.end[2]+n3; sa.end[4]=sa.end[3]+n4; sa.end[5]=sa.end[4]+n5;
    split_all_kernel<<<(sa.end[5] + 255)/256, 256>>>(sa);

    // (2) gating MLP (3-pass exact)
    gate_gemm<1><<<dim3(BB/128, G1/128), 256, SMEM3>>>(
        obs_h, obs_l, gw1h, gw1l, gb1, g1h, g1l, nullptr, DOBS, G1);
    // (3)
    gate_gemm<2><<<dim3(BB/128, G2/128), 256, SMEM3>>>(
        g1h, g1l, gw2h, gw2l, gb2, nullptr, nullptr, pg2, G1, G2);
    // (4) fused top-2 + renorm + scatter
    topk_scatter_kernel<<<BB/256, 256>>>(gw3, gb3);

    // (5)(6) expert layers 1-2 — launch #6 is e2 (ncu capture target)
    exp_gemm<true ><<<dim3(NE*128, E1/128), 256, SMEMX>>>(obs_h, ew1h, eb1, h1, DOBS, E1);
    exp_gemm<false><<<dim3(NE*128, E2/128), 256, SMEMX>>>(h1,    ew2h, eb2, h2, E1,   E2);

    // (7) zero output (needed before l4 atomics)
    cudaMemsetAsync(out, 0, (size_t)out_size * sizeof(float));

    // (8) expert layer 3
    exp_gemm<false><<<dim3(NE*128, E3/128), 256, SMEMX>>>(h2,    ew3h, eb3, h3, E2,   E3);

    // (9) layer 4 + weighted combine
    l4_combine_kernel<<<NE*128, 256>>>(ew4, eb4, out);
}

// round 12
// speedup vs baseline: 1.2206x; 1.2206x over previous
#include <cuda_runtime.h>
#include <cuda_fp16.h>
#include <cstdint>

#define BB   16384
#define DOBS 512
#define NE   8
#define NA   32
#define G1   256
#define G2   128
#define E1   1024
#define E2   512
#define E3   256
#define NP   (2*BB)

typedef __half h16;

// ---------------- scratch ----------------
__device__ __align__(16) h16 g_obs_h[BB*DOBS], g_obs_l[BB*DOBS];
__device__ __align__(16) h16 g_gw1h[DOBS*G1], g_gw1l[DOBS*G1];
__device__ __align__(16) h16 g_gw2h[G1*G2],   g_gw2l[G1*G2];
__device__ __align__(16) h16 g_ew1h[NE*DOBS*E1];
__device__ __align__(16) h16 g_ew2h[NE*E1*E2];
__device__ __align__(16) h16 g_ew3h[NE*E2*E3];

__device__ __align__(16) h16 g_g1h[BB*G1], g_g1l[BB*G1];
__device__ __align__(16) float g_g2[BB*G2];
__device__ __align__(16) h16 g_h1[(size_t)NP*E1];
__device__ __align__(16) h16 g_h2[(size_t)NP*E2];
__device__ __align__(16) h16 g_h3[(size_t)NP*E3];

__device__ int   g_tidx[BB*2];
__device__ float g_tw[BB*2];
__device__ int   g_counts[NE];
__device__ int   g_off[NE+1];
__device__ int   g_tile128[NE+1];
__device__ int   g_cursor[NE];
__device__ int   g_tok[NP];
__device__ float g_wt[NP];

__device__ __forceinline__ float eluf(float x) { return x > 0.f ? x : expm1f(x); }

// ---------------- PTX helpers ----------------
__device__ __forceinline__ void mma_f16(float* c, const unsigned* a, const unsigned* b) {
    asm volatile(
        "mma.sync.aligned.m16n8k16.row.col.f32.f16.f16.f32 "
        "{%0,%1,%2,%3}, {%4,%5,%6,%7}, {%8,%9}, {%0,%1,%2,%3};"
        : "+f"(c[0]), "+f"(c[1]), "+f"(c[2]), "+f"(c[3])
        : "r"(a[0]), "r"(a[1]), "r"(a[2]), "r"(a[3]), "r"(b[0]), "r"(b[1]));
}
__device__ __forceinline__ void ldsm_x4(unsigned* r, unsigned addr) {
    asm volatile("ldmatrix.sync.aligned.m8n8.x4.shared.b16 {%0,%1,%2,%3}, [%4];"
                 : "=r"(r[0]), "=r"(r[1]), "=r"(r[2]), "=r"(r[3]) : "r"(addr));
}
__device__ __forceinline__ void ldsm_x4_t(unsigned* r, unsigned addr) {
    asm volatile("ldmatrix.sync.aligned.m8n8.x4.trans.shared.b16 {%0,%1,%2,%3}, [%4];"
                 : "=r"(r[0]), "=r"(r[1]), "=r"(r[2]), "=r"(r[3]) : "r"(addr));
}
__device__ __forceinline__ uint32_t s2u(const void* p) {
    uint32_t a;
    asm("{ .reg .u64 t; cvta.to.shared.u64 t, %1; cvt.u32.u64 %0, t; }" : "=r"(a) : "l"(p));
    return a;
}
__device__ __forceinline__ void cpa16(uint32_t dst, const void* src, uint32_t sz) {
    asm volatile("cp.async.cg.shared.global [%0], [%1], 16, %2;" :: "r"(dst), "l"(src), "r"(sz) : "memory");
}
__device__ __forceinline__ void cpcommit() { asm volatile("cp.async.commit_group;" ::: "memory"); }
template<int N> __device__ __forceinline__ void cpwait() { asm volatile("cp.async.wait_group %0;" :: "n"(N) : "memory"); }

// ---------------- fused split: all fp32->fp16(hi/lo) conversions + counter init ----------------
struct SplitArgs {
    const float4* x[6];
    __half2*      hi[6];
    __half2*      lo[6];     // null => hi only
    unsigned      end[6];    // cumulative n4
};

__global__ __launch_bounds__(256)
void split_all_kernel(SplitArgs a)
{
    if (blockIdx.x == 0 && threadIdx.x < NE) {
        g_counts[threadIdx.x] = 0;
        g_cursor[threadIdx.x] = 0;
    }
    unsigned i = blockIdx.x * 256 + threadIdx.x;
    if (i >= a.end[5]) return;
    int s = 0;
    while (i >= a.end[s]) s++;
    unsigned base = s ? a.end[s-1] : 0;
    unsigned j = i - base;
    float4 v = a.x[s][j];
    h16 h0 = __float2half_rn(v.x), h1 = __float2half_rn(v.y);
    h16 h2 = __float2half_rn(v.z), h3 = __float2half_rn(v.w);
    a.hi[s][2*j]   = __halves2half2(h0, h1);
    a.hi[s][2*j+1] = __halves2half2(h2, h3);
    if (a.lo[s]) {
        a.lo[s][2*j]   = __halves2half2(__float2half_rn(v.x - __half2float(h0)),
                                        __float2half_rn(v.y - __half2float(h1)));
        a.lo[s][2*j+1] = __halves2half2(__float2half_rn(v.z - __half2float(h2)),
                                        __float2half_rn(v.w - __half2float(h3)));
    }
}

// ---------------- pipelined fp16 TC grouped GEMM (R8 config: 128x128, BK=32, 3-stage) ----------------
// NPASS==3 (gating): C = Ah@Bh + Ah@Bl + Al@Bh  (exact to ~1e-7)
// NPASS==1 (experts): C = A@Bh                   (plain fp16)
// OUTM: 0 = fp16 single, 1 = fp16 hi/lo, 2 = fp32
#define A_BYTES 10240   // 128 x 40 halves
#define B_BYTES 8704    // 32 x 136 halves

template<bool GROUPED, bool GATHER, int NPASS, int OUTM>
__global__ __launch_bounds__(256)
void mma_gemm(const h16* __restrict__ Ah, const h16* __restrict__ Al,
              const h16* __restrict__ Wh, const h16* __restrict__ Wl,
              const float* __restrict__ bias,
              h16* __restrict__ Ch, h16* __restrict__ Cl, float* __restrict__ Cf,
              int M, int K, int N)
{
    constexpr bool TRI = (NPASS == 3);
    constexpr uint32_t AL_OFF = A_BYTES;
    constexpr uint32_t BH_OFF = TRI ? 2*A_BYTES : A_BYTES;
    constexpr uint32_t BL_OFF = BH_OFF + B_BYTES;
    constexpr uint32_t STG    = BH_OFF + (TRI ? 2 : 1) * B_BYTES;

    extern __shared__ __align__(128) char sm[];
    int row0, rowEnd;
    if (GROUPED) {
        int bx = blockIdx.x;
        if (bx >= g_tile128[NE]) return;
        int e = 0;
        while (bx >= g_tile128[e+1]) e++;
        row0   = g_off[e] + (bx - g_tile128[e]) * 128;
        rowEnd = g_off[e+1];
        if (row0 >= rowEnd) return;
        Wh   += (size_t)e * K * N;
        if (TRI) Wl += (size_t)e * K * N;
        bias += e * N;
    } else {
        row0   = blockIdx.x * 128;
        rowEnd = M;
    }
    const int n0  = blockIdx.y * 128;
    const int tid = threadIdx.x, lane = tid & 31, wid = tid >> 5;
    const int warpM = wid & 3, warpN = wid >> 2;
    const uint32_t su = s2u(sm);

    const int ar  = tid >> 2;
    const int ach = tid & 3;
    const h16 *pAh[2], *pAl[2];
    uint32_t asz[2];
#pragma unroll
    for (int i = 0; i < 2; i++) {
        int gr = row0 + ar + 64*i;
        bool v = gr < rowEnd;
        asz[i] = v ? 16u : 0u;
        size_t rowIdx = 0;
        if (v) rowIdx = GATHER ? (size_t)g_tok[gr] : (size_t)gr;
        pAh[i] = Ah + rowIdx * K + ach*8;
        if (TRI) pAl[i] = Al + rowIdx * K + ach*8;
    }
    const int br  = tid >> 4;
    const int bch = tid & 15;
    const h16* pBh = Wh + (size_t)br * N + n0 + bch*8;
    const h16* pBl = TRI ? (Wl + (size_t)br * N + n0 + bch*8) : nullptr;

    float acc[2][8][4];
#pragma unroll
    for (int mt = 0; mt < 2; mt++)
#pragma unroll
        for (int nt = 0; nt < 8; nt++)
#pragma unroll
            for (int q = 0; q < 4; q++) acc[mt][nt][q] = 0.f;

    const int S = K >> 5;

    auto LOAD = [&](int t) {
        uint32_t base = su + (uint32_t)(t % 3) * STG;
        int kf = t * 32;
#pragma unroll
        for (int i = 0; i < 2; i++) {
            uint32_t d = base + (uint32_t)((ar + 64*i)*80 + ach*16);
            cpa16(d, pAh[i] + kf, asz[i]);
            if (TRI) cpa16(d + AL_OFF, pAl[i] + kf, asz[i]);
        }
#pragma unroll
        for (int i = 0; i < 2; i++) {
            uint32_t d = base + (uint32_t)((br + 16*i)*272 + bch*16);
            cpa16(d + BH_OFF, pBh + (size_t)(kf + 16*i) * N, 16u);
            if (TRI) cpa16(d + BL_OFF, pBl + (size_t)(kf + 16*i) * N, 16u);
        }
        cpcommit();
    };

    LOAD(0);
    LOAD(1);

    for (int s = 0; s < S; s++) {
        __syncthreads();
        int rem = S - 1 - s;
        if (rem >= 2) { LOAD(s+2); cpwait<2>(); }
        else if (rem == 1) cpwait<1>();
        else cpwait<0>();
        __syncthreads();

        const uint32_t aBase = su + (uint32_t)(s % 3) * STG;
#pragma unroll
        for (int kk = 0; kk < 32; kk += 16) {
            unsigned ah[2][4], al[2][4];
#pragma unroll
            for (int mt = 0; mt < 2; mt++) {
                uint32_t off = (uint32_t)(((warpM*32 + mt*16 + (lane & 15))*40 + kk + 8*(lane >> 4)) * 2);
                ldsm_x4(ah[mt], aBase + off);
                if (TRI) ldsm_x4(al[mt], aBase + AL_OFF + off);
            }
            const int brow = kk + (lane & 15);
#pragma unroll
            for (int np = 0; np < 4; np++) {
                const int bcol = warpN*64 + np*16 + 8*(lane >> 4);
                uint32_t boff = (uint32_t)((brow*136 + bcol) * 2);
                unsigned bh[4], bl[4];
                ldsm_x4_t(bh, aBase + BH_OFF + boff);
                if (TRI) ldsm_x4_t(bl, aBase + BL_OFF + boff);
#pragma unroll
                for (int mt = 0; mt < 2; mt++) {
                    mma_f16(acc[mt][2*np],   ah[mt], bh);
                    mma_f16(acc[mt][2*np+1], ah[mt], bh+2);
                    if (TRI) {
                        mma_f16(acc[mt][2*np],   ah[mt], bl);
                        mma_f16(acc[mt][2*np+1], ah[mt], bl+2);
                        mma_f16(acc[mt][2*np],   al[mt], bh);
                        mma_f16(acc[mt][2*np+1], al[mt], bh+2);
                    }
                }
            }
        }
    }

    // ---------------- epilogue ----------------
#pragma unroll
    for (int mt = 0; mt < 2; mt++) {
        int r0 = row0 + warpM*32 + mt*16 + (lane >> 2);
#pragma unroll
        for (int nt = 0; nt < 8; nt++) {
            int c = n0 + warpN*64 + nt*8 + 2*(lane & 3);
            float b0 = __ldg(bias + c), b1 = __ldg(bias + c + 1);
            float v00 = eluf(acc[mt][nt][0] + b0);
            float v01 = eluf(acc[mt][nt][1] + b1);
            float v10 = eluf(acc[mt][nt][2] + b0);
            float v11 = eluf(acc[mt][nt][3] + b1);
#pragma unroll
            for (int rr = 0; rr < 2; rr++) {
                int r = r0 + rr*8;
                float va = rr ? v10 : v00, vb = rr ? v11 : v01;
                if (r < rowEnd) {
                    if (OUTM == 0) {
                        *(__half2*)(Ch + (size_t)r*N + c) =
                            __halves2half2(__float2half_rn(va), __float2half_rn(vb));
                    } else if (OUTM == 1) {
                        h16 h0 = __float2half_rn(va), h1 = __float2half_rn(vb);
                        *(__half2*)(Ch + (size_t)r*N + c) = __halves2half2(h0, h1);
                        *(__half2*)(Cl + (size_t)r*N + c) =
                            __halves2half2(__float2half_rn(va - __half2float(h0)),
                                           __float2half_rn(vb - __half2float(h1)));
                    } else {
                        *(float2*)(Cf + (size_t)r*N + c) = make_float2(va, vb);
                    }
                }
            }
        }
    }
}

// ---------------- gating head: one thread per token ----------------
__global__ __launch_bounds__(256)
void gate_topk_kernel(const float* __restrict__ gw3, const float* __restrict__ gb3)
{
    __shared__ float sW[G2*NE];
    __shared__ float sB[NE];
    const int tid = threadIdx.x;
    for (int i = tid; i < G2*NE; i += 256) sW[i] = gw3[i];
    if (tid < NE) sB[tid] = gb3[tid];
    __syncthreads();

    const int b = blockIdx.x * 256 + tid;
    const float4* g = (const float4*)(g_g2 + (size_t)b * G2);
    float lg[NE];
#pragma unroll
    for (int j = 0; j < NE; j++) lg[j] = sB[j];
#pragma unroll 4
    for (int k4 = 0; k4 < G2/4; k4++) {
        float4 v = g[k4];
        const float* w = sW + k4*4*NE;
#pragma unroll
        for (int j = 0; j < NE; j++)
            lg[j] += v.x*w[j] + v.y*w[NE+j] + v.z*w[2*NE+j] + v.w*w[3*NE+j];
    }
    int i0 = 0; float m0 = lg[0];
#pragma unroll
    for (int j = 1; j < NE; j++) if (lg[j] > m0) { m0 = lg[j]; i0 = j; }
    int i1 = -1; float m1 = -3.4e38f;
#pragma unroll
    for (int j = 0; j < NE; j++) if (j != i0 && lg[j] > m1) { m1 = lg[j]; i1 = j; }
    float e1  = expf(m1 - m0);
    float inv = 1.f / (1.f + e1);
    g_tidx[b*2+0] = i0; g_tidx[b*2+1] = i1;
    g_tw[b*2+0] = inv;  g_tw[b*2+1] = e1 * inv;
    atomicAdd(&g_counts[i0], 1);
    atomicAdd(&g_counts[i1], 1);
}

// ---------------- prefix sums ----------------
__global__ void offsets_kernel()
{
    if (threadIdx.x == 0 && blockIdx.x == 0) {
        int o = 0, t128 = 0;
        for (int e = 0; e < NE; e++) {
            g_off[e] = o; g_tile128[e] = t128;
            int c = g_counts[e];
            o += c; t128 += (c + 127) >> 7;
        }
        g_off[NE] = o; g_tile128[NE] = t128;
    }
}

// ---------------- scatter ----------------
__global__ __launch_bounds__(256)
void scatter_kernel()
{
    const int b    = blockIdx.x * 256 + threadIdx.x;
    const int lane = threadIdx.x & 31;
#pragma unroll
    for (int s = 0; s < 2; s++) {
        int   e = g_tidx[b*2 + s];
        float w = g_tw[b*2 + s];
#pragma unroll
        for (int ee = 0; ee < NE; ee++) {
            unsigned m = __ballot_sync(0xffffffffu, e == ee);
            if (e == ee) {
                int rank   = __popc(m & ((1u << lane) - 1u));
                int leader = __ffs(m) - 1;
                int base = 0;
                if (lane == leader) base = atomicAdd(&g_cursor[ee], __popc(m));
                base = __shfl_sync(m, base, leader);
                int p = g_off[ee] + base + rank;
                g_tok[p] = b; g_wt[p] = w;
            }
        }
    }
}

// ---------------- layer 4 (K=256, N=32) + weighted combine, 128 rows/block ----------------
__global__ __launch_bounds__(256)
void l4_combine_kernel(const float* __restrict__ W4, const float* __restrict__ B4,
                       float* __restrict__ out)
{
    const int bx = blockIdx.x;
    if (bx >= g_tile128[NE]) return;
    int e = 0;
    while (bx >= g_tile128[e+1]) e++;
    const int row0   = g_off[e] + (bx - g_tile128[e]) * 128;
    const int rowEnd = g_off[e+1];

    __shared__ float sW[E3*NA];
    const float* We = W4 + (size_t)e * E3 * NA;
    for (int i = threadIdx.x; i < E3*NA/4; i += 256)
        *(float4*)&sW[i*4] = *(const float4*)&We[i*4];
    __syncthreads();

    const int r  = threadIdx.x >> 3;
    const int c4 = (threadIdx.x & 7) * 4;
    const float bb0 = B4[e*NA + c4 + 0], bb1 = B4[e*NA + c4 + 1];
    const float bb2 = B4[e*NA + c4 + 2], bb3 = B4[e*NA + c4 + 3];

#pragma unroll
    for (int it = 0; it < 4; it++) {
        const int row = row0 + r + 32*it;
        if (row >= rowEnd) break;
        const __half2* hh = (const __half2*)(g_h3 + (size_t)row * E3);
        float a0 = 0.f, a1 = 0.f, a2 = 0.f, a3 = 0.f;
#pragma unroll 4
        for (int k = 0; k < E3; k += 4) {
            float2 p0 = __half22float2(hh[k/2]);
            float2 p1 = __half22float2(hh[k/2+1]);
            float4 w0 = *(float4*)&sW[(k+0)*NA + c4];
            float4 w1 = *(float4*)&sW[(k+1)*NA + c4];
            float4 w2 = *(float4*)&sW[(k+2)*NA + c4];
            float4 w3 = *(float4*)&sW[(k+3)*NA + c4];
            a0 += p0.x*w0.x + p0.y*w1.x + p1.x*w2.x + p1.y*w3.x;
            a1 += p0.x*w0.y + p0.y*w1.y + p1.x*w2.y + p1.y*w3.y;
            a2 += p0.x*w0.z + p0.y*w1.z + p1.x*w2.z + p1.y*w3.z;
            a3 += p0.x*w0.w + p0.y*w1.w + p1.x*w2.w + p1.y*w3.w;
        }
        const int   tok = g_tok[row];
        const float w   = g_wt[row];
        float* o = out + (size_t)tok * NA + c4;
        atomicAdd(o+0, w*(a0 + bb0));
        atomicAdd(o+1, w*(a1 + bb1));
        atomicAdd(o+2, w*(a2 + bb2));
        atomicAdd(o+3, w*(a3 + bb3));
    }
}

// ---------------- launch ----------------
#define SMEM3 (3 * (2*A_BYTES + 2*B_BYTES))   // 113664 (gating)
#define SMEM1 (3 * (A_BYTES + B_BYTES))       //  56832 (experts)

extern "C" void kernel_launch(void* const* d_in, const int* in_sizes, int n_in,
                              void* d_out, int out_size)
{
    const float* obs = (const float*)d_in[0];
    const float* gw1 = (const float*)d_in[1];
    const float* gb1 = (const float*)d_in[2];
    const float* gw2 = (const float*)d_in[3];
    const float* gb2 = (const float*)d_in[4];
    const float* gw3 = (const float*)d_in[5];
    const float* gb3 = (const float*)d_in[6];
    const float* ew1 = (const float*)d_in[7];
    const float* eb1 = (const float*)d_in[8];
    const float* ew2 = (const float*)d_in[9];
    const float* eb2 = (const float*)d_in[10];
    const float* ew3 = (const float*)d_in[11];
    const float* eb3 = (const float*)d_in[12];
    const float* ew4 = (const float*)d_in[13];
    const float* eb4 = (const float*)d_in[14];
    float* out = (float*)d_out;

    h16 *obs_h, *obs_l, *gw1h, *gw1l, *gw2h, *gw2l;
    h16 *ew1h, *ew2h, *ew3h;
    h16 *g1h, *g1l, *h1, *h2, *h3;
    float *pg2;
    cudaGetSymbolAddress((void**)&obs_h, g_obs_h); cudaGetSymbolAddress((void**)&obs_l, g_obs_l);
    cudaGetSymbolAddress((void**)&gw1h, g_gw1h);   cudaGetSymbolAddress((void**)&gw1l, g_gw1l);
    cudaGetSymbolAddress((void**)&gw2h, g_gw2h);   cudaGetSymbolAddress((void**)&gw2l, g_gw2l);
    cudaGetSymbolAddress((void**)&ew1h, g_ew1h);
    cudaGetSymbolAddress((void**)&ew2h, g_ew2h);
    cudaGetSymbolAddress((void**)&ew3h, g_ew3h);
    cudaGetSymbolAddress((void**)&g1h, g_g1h);     cudaGetSymbolAddress((void**)&g1l, g_g1l);
    cudaGetSymbolAddress((void**)&h1, g_h1);
    cudaGetSymbolAddress((void**)&h2, g_h2);
    cudaGetSymbolAddress((void**)&h3, g_h3);
    cudaGetSymbolAddress((void**)&pg2, g_g2);

    cudaFuncSetAttribute(mma_gemm<false,false,3,1>, cudaFuncAttributeMaxDynamicSharedMemorySize, SMEM3);
    cudaFuncSetAttribute(mma_gemm<false,false,3,2>, cudaFuncAttributeMaxDynamicSharedMemorySize, SMEM3);
    cudaFuncSetAttribute(mma_gemm<true ,true ,1,0>, cudaFuncAttributeMaxDynamicSharedMemorySize, SMEM1);
    cudaFuncSetAttribute(mma_gemm<true ,false,1,0>, cudaFuncAttributeMaxDynamicSharedMemorySize, SMEM1);

    cudaMemsetAsync(out, 0, (size_t)out_size * sizeof(float));

    // fused splits (also zeroes counters)
    SplitArgs sa;
    unsigned n0 = BB*DOBS/4, n1 = DOBS*G1/4, n2 = G1*G2/4;
    unsigned n3 = NE*DOBS*E1/4, n4 = NE*E1*E2/4, n5 = NE*E2*E3/4;
    sa.x[0]=(const float4*)obs; sa.hi[0]=(__half2*)obs_h; sa.lo[0]=(__half2*)obs_l;
    sa.x[1]=(const float4*)gw1; sa.hi[1]=(__half2*)gw1h;  sa.lo[1]=(__half2*)gw1l;
    sa.x[2]=(const float4*)gw2; sa.hi[2]=(__half2*)gw2h;  sa.lo[2]=(__half2*)gw2l;
    sa.x[3]=(const float4*)ew1; sa.hi[3]=(__half2*)ew1h;  sa.lo[3]=nullptr;
    sa.x[4]=(const float4*)ew2; sa.hi[4]=(__half2*)ew2h;  sa.lo[4]=nullptr;
    sa.x[5]=(const float4*)ew3; sa.hi[5]=(__half2*)ew3h;  sa.lo[5]=nullptr;
    sa.end[0]=n0; sa.end[1]=n0+n1; sa.end[2]=n0+n1+n2;
    sa.end[3]=sa.end[2]+n3; sa.end[4]=sa.end[3]+n4; sa.end[5]=sa.end[4]+n5;
    split_all_kernel<<<(sa.end[5] + 255)/256, 256>>>(sa);

    // gating MLP: 3-pass exact
    mma_gemm<false,false,3,1><<<dim3(BB/128, G1/128), 256, SMEM3>>>(
        obs_h, obs_l, gw1h, gw1l, gb1, g1h, g1l, nullptr, BB, DOBS, G1);
    mma_gemm<false,false,3,2><<<dim3(BB/128, G2/128), 256, SMEM3>>>(
        g1h, g1l, gw2h, gw2l, gb2, nullptr, nullptr, pg2, BB, G1, G2);
    gate_topk_kernel<<<BB/256, 256>>>(gw3, gb3);
    offsets_kernel<<<1, 32>>>();
    scatter_kernel<<<BB/256, 256>>>();

    // grouped expert layers: single-pass fp16 (R8 config)
    const int T128 = NP/128 + NE;   // 264
    mma_gemm<true,true ,1,0><<<dim3(T128, E1/128), 256, SMEM1>>>(
        obs_h, nullptr, ew1h, nullptr, eb1, h1, nullptr, nullptr, 0, DOBS, E1);
    mma_gemm<true,false,1,0><<<dim3(T128, E2/128), 256, SMEM1>>>(
        h1, nullptr, ew2h, nullptr, eb2, h2, nullptr, nullptr, 0, E1, E2);
    mma_gemm<true,false,1,0><<<dim3(T128, E3/128), 256, SMEM1>>>(
        h2, nullptr, ew3h, nullptr, eb3, h3, nullptr, nullptr, 0, E2, E3);

    // layer 4 + weighted combine
    l4_combine_kernel<<<T128, 256>>>(ew4, eb4, out);
}

// round 13
// speedup vs baseline: 1.2219x; 1.0010x over previous
#include <cuda_runtime.h>
#include <cuda_fp16.h>
#include <cstdint>

#define BB   16384
#define DOBS 512
#define NE   8
#define NA   32
#define G1   256
#define G2   128
#define E1   1024
#define E2   512
#define E3   256
#define NP   (2*BB)

typedef __half h16;

// ---------------- scratch ----------------
__device__ __align__(16) h16 g_obs_h[BB*DOBS], g_obs_l[BB*DOBS];
__device__ __align__(16) h16 g_gw1h[DOBS*G1], g_gw1l[DOBS*G1];
__device__ __align__(16) h16 g_gw2h[G1*G2],   g_gw2l[G1*G2];
__device__ __align__(16) h16 g_ew1h[NE*DOBS*E1];
__device__ __align__(16) h16 g_ew2h[NE*E1*E2];
__device__ __align__(16) h16 g_ew3h[NE*E2*E3];

__device__ __align__(16) h16 g_g1h[BB*G1], g_g1l[BB*G1];
__device__ __align__(16) float g_g2[BB*G2];
__device__ __align__(16) h16 g_h1[(size_t)NP*E1];
__device__ __align__(16) h16 g_h2[(size_t)NP*E2];
__device__ __align__(16) h16 g_h3[(size_t)NP*E3];

__device__ int   g_tidx[BB*2];
__device__ float g_tw[BB*2];
__device__ int   g_counts[NE];
__device__ int   g_off[NE+1];
__device__ int   g_tile128[NE+1];
__device__ int   g_cursor[NE];
__device__ int   g_tok[NP];
__device__ float g_wt[NP];

__device__ __forceinline__ float eluf(float x) { return x > 0.f ? x : expm1f(x); }

// ---------------- PTX helpers ----------------
__device__ __forceinline__ void mma_f16(float* c, const unsigned* a, const unsigned* b) {
    asm volatile(
        "mma.sync.aligned.m16n8k16.row.col.f32.f16.f16.f32 "
        "{%0,%1,%2,%3}, {%4,%5,%6,%7}, {%8,%9}, {%0,%1,%2,%3};"
        : "+f"(c[0]), "+f"(c[1]), "+f"(c[2]), "+f"(c[3])
        : "r"(a[0]), "r"(a[1]), "r"(a[2]), "r"(a[3]), "r"(b[0]), "r"(b[1]));
}
__device__ __forceinline__ void ldsm_x4(unsigned* r, unsigned addr) {
    asm volatile("ldmatrix.sync.aligned.m8n8.x4.shared.b16 {%0,%1,%2,%3}, [%4];"
                 : "=r"(r[0]), "=r"(r[1]), "=r"(r[2]), "=r"(r[3]) : "r"(addr));
}
__device__ __forceinline__ void ldsm_x4_t(unsigned* r, unsigned addr) {
    asm volatile("ldmatrix.sync.aligned.m8n8.x4.trans.shared.b16 {%0,%1,%2,%3}, [%4];"
                 : "=r"(r[0]), "=r"(r[1]), "=r"(r[2]), "=r"(r[3]) : "r"(addr));
}
__device__ __forceinline__ uint32_t s2u(const void* p) {
    uint32_t a;
    asm("{ .reg .u64 t; cvta.to.shared.u64 t, %1; cvt.u32.u64 %0, t; }" : "=r"(a) : "l"(p));
    return a;
}
__device__ __forceinline__ void cpa16(uint32_t dst, const void* src, uint32_t sz) {
    asm volatile("cp.async.cg.shared.global [%0], [%1], 16, %2;" :: "r"(dst), "l"(src), "r"(sz) : "memory");
}
__device__ __forceinline__ void cpcommit() { asm volatile("cp.async.commit_group;" ::: "memory"); }
template<int N> __device__ __forceinline__ void cpwait() { asm volatile("cp.async.wait_group %0;" :: "n"(N) : "memory"); }

// ---------------- fused split: all fp32->fp16(hi/lo) conversions + counter init ----------------
struct SplitArgs {
    const float4* x[6];
    __half2*      hi[6];
    __half2*      lo[6];     // null => hi only
    unsigned      end[6];    // cumulative n4
};

__global__ __launch_bounds__(256)
void split_all_kernel(SplitArgs a)
{
    if (blockIdx.x == 0 && threadIdx.x < NE) {
        g_counts[threadIdx.x] = 0;
        g_cursor[threadIdx.x] = 0;
    }
    unsigned i = blockIdx.x * 256 + threadIdx.x;
    if (i >= a.end[5]) return;
    int s = 0;
    while (i >= a.end[s]) s++;
    unsigned base = s ? a.end[s-1] : 0;
    unsigned j = i - base;
    float4 v = a.x[s][j];
    h16 h0 = __float2half_rn(v.x), h1 = __float2half_rn(v.y);
    h16 h2 = __float2half_rn(v.z), h3 = __float2half_rn(v.w);
    a.hi[s][2*j]   = __halves2half2(h0, h1);
    a.hi[s][2*j+1] = __halves2half2(h2, h3);
    if (a.lo[s]) {
        a.lo[s][2*j]   = __halves2half2(__float2half_rn(v.x - __half2float(h0)),
                                        __float2half_rn(v.y - __half2float(h1)));
        a.lo[s][2*j+1] = __halves2half2(__float2half_rn(v.z - __half2float(h2)),
                                        __float2half_rn(v.w - __half2float(h3)));
    }
}

// ---------------- pipelined fp16 TC grouped GEMM (128x128, BK=32, 3-stage) ----------------
// GRID TRANSPOSED: blockIdx.x = n-tile (fast -> concurrent blocks share A tile in L2),
//                  blockIdx.y = row tile (grouped dispatch for experts).
// NPASS==3 (gating): C = Ah@Bh + Ah@Bl + Al@Bh  (exact to ~1e-7)
// NPASS==1 (experts): C = A@Bh                   (plain fp16)
// OUTM: 0 = fp16 single, 1 = fp16 hi/lo, 2 = fp32
#define A_BYTES 10240   // 128 x 40 halves
#define B_BYTES 8704    // 32 x 136 halves

template<bool GROUPED, bool GATHER, int NPASS, int OUTM>
__global__ __launch_bounds__(256)
void mma_gemm(const h16* __restrict__ Ah, const h16* __restrict__ Al,
              const h16* __restrict__ Wh, const h16* __restrict__ Wl,
              const float* __restrict__ bias,
              h16* __restrict__ Ch, h16* __restrict__ Cl, float* __restrict__ Cf,
              int M, int K, int N)
{
    constexpr bool TRI = (NPASS == 3);
    constexpr uint32_t AL_OFF = A_BYTES;
    constexpr uint32_t BH_OFF = TRI ? 2*A_BYTES : A_BYTES;
    constexpr uint32_t BL_OFF = BH_OFF + B_BYTES;
    constexpr uint32_t STG    = BH_OFF + (TRI ? 2 : 1) * B_BYTES;

    extern __shared__ __align__(128) char sm[];
    int row0, rowEnd;
    if (GROUPED) {
        int bx = blockIdx.y;
        if (bx >= g_tile128[NE]) return;
        int e = 0;
        while (bx >= g_tile128[e+1]) e++;
        row0   = g_off[e] + (bx - g_tile128[e]) * 128;
        rowEnd = g_off[e+1];
        if (row0 >= rowEnd) return;
        Wh   += (size_t)e * K * N;
        if (TRI) Wl += (size_t)e * K * N;
        bias += e * N;
    } else {
        row0   = blockIdx.y * 128;
        rowEnd = M;
    }
    const int n0  = blockIdx.x * 128;
    const int tid = threadIdx.x, lane = tid & 31, wid = tid >> 5;
    const int warpM = wid & 3, warpN = wid >> 2;
    const uint32_t su = s2u(sm);

    const int ar  = tid >> 2;
    const int ach = tid & 3;
    const h16 *pAh[2], *pAl[2];
    uint32_t asz[2];
#pragma unroll
    for (int i = 0; i < 2; i++) {
        int gr = row0 + ar + 64*i;
        bool v = gr < rowEnd;
        asz[i] = v ? 16u : 0u;
        size_t rowIdx = 0;
        if (v) rowIdx = GATHER ? (size_t)g_tok[gr] : (size_t)gr;
        pAh[i] = Ah + rowIdx * K + ach*8;
        if (TRI) pAl[i] = Al + rowIdx * K + ach*8;
    }
    const int br  = tid >> 4;
    const int bch = tid & 15;
    const h16* pBh = Wh + (size_t)br * N + n0 + bch*8;
    const h16* pBl = TRI ? (Wl + (size_t)br * N + n0 + bch*8) : nullptr;

    float acc[2][8][4];
#pragma unroll
    for (int mt = 0; mt < 2; mt++)
#pragma unroll
        for (int nt = 0; nt < 8; nt++)
#pragma unroll
            for (int q = 0; q < 4; q++) acc[mt][nt][q] = 0.f;

    const int S = K >> 5;

    auto LOAD = [&](int t) {
        uint32_t base = su + (uint32_t)(t % 3) * STG;
        int kf = t * 32;
#pragma unroll
        for (int i = 0; i < 2; i++) {
            uint32_t d = base + (uint32_t)((ar + 64*i)*80 + ach*16);
            cpa16(d, pAh[i] + kf, asz[i]);
            if (TRI) cpa16(d + AL_OFF, pAl[i] + kf, asz[i]);
        }
#pragma unroll
        for (int i = 0; i < 2; i++) {
            uint32_t d = base + (uint32_t)((br + 16*i)*272 + bch*16);
            cpa16(d + BH_OFF, pBh + (size_t)(kf + 16*i) * N, 16u);
            if (TRI) cpa16(d + BL_OFF, pBl + (size_t)(kf + 16*i) * N, 16u);
        }
        cpcommit();
    };

    LOAD(0);
    LOAD(1);

    for (int s = 0; s < S; s++) {
        __syncthreads();
        int rem = S - 1 - s;
        if (rem >= 2) { LOAD(s+2); cpwait<2>(); }
        else if (rem == 1) cpwait<1>();
        else cpwait<0>();
        __syncthreads();

        const uint32_t aBase = su + (uint32_t)(s % 3) * STG;
#pragma unroll
        for (int kk = 0; kk < 32; kk += 16) {
            unsigned ah[2][4], al[2][4];
#pragma unroll
            for (int mt = 0; mt < 2; mt++) {
                uint32_t off = (uint32_t)(((warpM*32 + mt*16 + (lane & 15))*40 + kk + 8*(lane >> 4)) * 2);
                ldsm_x4(ah[mt], aBase + off);
                if (TRI) ldsm_x4(al[mt], aBase + AL_OFF + off);
            }
            const int brow = kk + (lane & 15);
#pragma unroll
            for (int np = 0; np < 4; np++) {
                const int bcol = warpN*64 + np*16 + 8*(lane >> 4);
                uint32_t boff = (uint32_t)((brow*136 + bcol) * 2);
                unsigned bh[4], bl[4];
                ldsm_x4_t(bh, aBase + BH_OFF + boff);
                if (TRI) ldsm_x4_t(bl, aBase + BL_OFF + boff);
#pragma unroll
                for (int mt = 0; mt < 2; mt++) {
                    mma_f16(acc[mt][2*np],   ah[mt], bh);
                    mma_f16(acc[mt][2*np+1], ah[mt], bh+2);
                    if (TRI) {
                        mma_f16(acc[mt][2*np],   ah[mt], bl);
                        mma_f16(acc[mt][2*np+1], ah[mt], bl+2);
                        mma_f16(acc[mt][2*np],   al[mt], bh);
                        mma_f16(acc[mt][2*np+1], al[mt], bh+2);
                    }
                }
            }
        }
    }

    // ---------------- epilogue ----------------
#pragma unroll
    for (int mt = 0; mt < 2; mt++) {
        int r0 = row0 + warpM*32 + mt*16 + (lane >> 2);
#pragma unroll
        for (int nt = 0; nt < 8; nt++) {
            int c = n0 + warpN*64 + nt*8 + 2*(lane & 3);
            float b0 = __ldg(bias + c), b1 = __ldg(bias + c + 1);
            float v00 = eluf(acc[mt][nt][0] + b0);
            float v01 = eluf(acc[mt][nt][1] + b1);
            float v10 = eluf(acc[mt][nt][2] + b0);
            float v11 = eluf(acc[mt][nt][3] + b1);
#pragma unroll
            for (int rr = 0; rr < 2; rr++) {
                int r = r0 + rr*8;
                float va = rr ? v10 : v00, vb = rr ? v11 : v01;
                if (r < rowEnd) {
                    if (OUTM == 0) {
                        *(__half2*)(Ch + (size_t)r*N + c) =
                            __halves2half2(__float2half_rn(va), __float2half_rn(vb));
                    } else if (OUTM == 1) {
                        h16 h0 = __float2half_rn(va), h1 = __float2half_rn(vb);
                        *(__half2*)(Ch + (size_t)r*N + c) = __halves2half2(h0, h1);
                        *(__half2*)(Cl + (size_t)r*N + c) =
                            __halves2half2(__float2half_rn(va - __half2float(h0)),
                                           __float2half_rn(vb - __half2float(h1)));
                    } else {
                        *(float2*)(Cf + (size_t)r*N + c) = make_float2(va, vb);
                    }
                }
            }
        }
    }
}

// ---------------- gating head: one thread per token ----------------
__global__ __launch_bounds__(256)
void gate_topk_kernel(const float* __restrict__ gw3, const float* __restrict__ gb3)
{
    __shared__ float sW[G2*NE];
    __shared__ float sB[NE];
    const int tid = threadIdx.x;
    for (int i = tid; i < G2*NE; i += 256) sW[i] = gw3[i];
    if (tid < NE) sB[tid] = gb3[tid];
    __syncthreads();

    const int b = blockIdx.x * 256 + tid;
    const float4* g = (const float4*)(g_g2 + (size_t)b * G2);
    float lg[NE];
#pragma unroll
    for (int j = 0; j < NE; j++) lg[j] = sB[j];
#pragma unroll 4
    for (int k4 = 0; k4 < G2/4; k4++) {
        float4 v = g[k4];
        const float* w = sW + k4*4*NE;
#pragma unroll
        for (int j = 0; j < NE; j++)
            lg[j] += v.x*w[j] + v.y*w[NE+j] + v.z*w[2*NE+j] + v.w*w[3*NE+j];
    }
    int i0 = 0; float m0 = lg[0];
#pragma unroll
    for (int j = 1; j < NE; j++) if (lg[j] > m0) { m0 = lg[j]; i0 = j; }
    int i1 = -1; float m1 = -3.4e38f;
#pragma unroll
    for (int j = 0; j < NE; j++) if (j != i0 && lg[j] > m1) { m1 = lg[j]; i1 = j; }
    float e1  = expf(m1 - m0);
    float inv = 1.f / (1.f + e1);
    g_tidx[b*2+0] = i0; g_tidx[b*2+1] = i1;
    g_tw[b*2+0] = inv;  g_tw[b*2+1] = e1 * inv;
    atomicAdd(&g_counts[i0], 1);
    atomicAdd(&g_counts[i1], 1);
}

// ---------------- prefix sums ----------------
__global__ void offsets_kernel()
{
    if (threadIdx.x == 0 && blockIdx.x == 0) {
        int o = 0, t128 = 0;
        for (int e = 0; e < NE; e++) {
            g_off[e] = o; g_tile128[e] = t128;
            int c = g_counts[e];
            o += c; t128 += (c + 127) >> 7;
        }
        g_off[NE] = o; g_tile128[NE] = t128;
    }
}

// ---------------- scatter ----------------
__global__ __launch_bounds__(256)
void scatter_kernel()
{
    const int b    = blockIdx.x * 256 + threadIdx.x;
    const int lane = threadIdx.x & 31;
#pragma unroll
    for (int s = 0; s < 2; s++) {
        int   e = g_tidx[b*2 + s];
        float w = g_tw[b*2 + s];
#pragma unroll
        for (int ee = 0; ee < NE; ee++) {
            unsigned m = __ballot_sync(0xffffffffu, e == ee);
            if (e == ee) {
                int rank   = __popc(m & ((1u << lane) - 1u));
                int leader = __ffs(m) - 1;
                int base = 0;
                if (lane == leader) base = atomicAdd(&g_cursor[ee], __popc(m));
                base = __shfl_sync(m, base, leader);
                int p = g_off[ee] + base + rank;
                g_tok[p] = b; g_wt[p] = w;
            }
        }
    }
}

// ---------------- layer 4 (K=256, N=32) + weighted combine, 128 rows/block ----------------
__global__ __launch_bounds__(256)
void l4_combine_kernel(const float* __restrict__ W4, const float* __restrict__ B4,
                       float* __restrict__ out)
{
    const int bx = blockIdx.x;
    if (bx >= g_tile128[NE]) return;
    int e = 0;
    while (bx >= g_tile128[e+1]) e++;
    const int row0   = g_off[e] + (bx - g_tile128[e]) * 128;
    const int rowEnd = g_off[e+1];

    __shared__ float sW[E3*NA];
    const float* We = W4 + (size_t)e * E3 * NA;
    for (int i = threadIdx.x; i < E3*NA/4; i += 256)
        *(float4*)&sW[i*4] = *(const float4*)&We[i*4];
    __syncthreads();

    const int r  = threadIdx.x >> 3;
    const int c4 = (threadIdx.x & 7) * 4;
    const float bb0 = B4[e*NA + c4 + 0], bb1 = B4[e*NA + c4 + 1];
    const float bb2 = B4[e*NA + c4 + 2], bb3 = B4[e*NA + c4 + 3];

#pragma unroll
    for (int it = 0; it < 4; it++) {
        const int row = row0 + r + 32*it;
        if (row >= rowEnd) break;
        const __half2* hh = (const __half2*)(g_h3 + (size_t)row * E3);
        float a0 = 0.f, a1 = 0.f, a2 = 0.f, a3 = 0.f;
#pragma unroll 4
        for (int k = 0; k < E3; k += 4) {
            float2 p0 = __half22float2(hh[k/2]);
            float2 p1 = __half22float2(hh[k/2+1]);
            float4 w0 = *(float4*)&sW[(k+0)*NA + c4];
            float4 w1 = *(float4*)&sW[(k+1)*NA + c4];
            float4 w2 = *(float4*)&sW[(k+2)*NA + c4];
            float4 w3 = *(float4*)&sW[(k+3)*NA + c4];
            a0 += p0.x*w0.x + p0.y*w1.x + p1.x*w2.x + p1.y*w3.x;
            a1 += p0.x*w0.y + p0.y*w1.y + p1.x*w2.y + p1.y*w3.y;
            a2 += p0.x*w0.z + p0.y*w1.z + p1.x*w2.z + p1.y*w3.z;
            a3 += p0.x*w0.w + p0.y*w1.w + p1.x*w2.w + p1.y*w3.w;
        }
        const int   tok = g_tok[row];
        const float w   = g_wt[row];
        float* o = out + (size_t)tok * NA + c4;
        atomicAdd(o+0, w*(a0 + bb0));
        atomicAdd(o+1, w*(a1 + bb1));
        atomicAdd(o+2, w*(a2 + bb2));
        atomicAdd(o+3, w*(a3 + bb3));
    }
}

// ---------------- launch ----------------
#define SMEM3 (3 * (2*A_BYTES + 2*B_BYTES))   // 113664 (gating)
#define SMEM1 (3 * (A_BYTES + B_BYTES))       //  56832 (experts)

extern "C" void kernel_launch(void* const* d_in, const int* in_sizes, int n_in,
                              void* d_out, int out_size)
{
    const float* obs = (const float*)d_in[0];
    const float* gw1 = (const float*)d_in[1];
    const float* gb1 = (const float*)d_in[2];
    const float* gw2 = (const float*)d_in[3];
    const float* gb2 = (const float*)d_in[4];
    const float* gw3 = (const float*)d_in[5];
    const float* gb3 = (const float*)d_in[6];
    const float* ew1 = (const float*)d_in[7];
    const float* eb1 = (const float*)d_in[8];
    const float* ew2 = (const float*)d_in[9];
    const float* eb2 = (const float*)d_in[10];
    const float* ew3 = (const float*)d_in[11];
    const float* eb3 = (const float*)d_in[12];
    const float* ew4 = (const float*)d_in[13];
    const float* eb4 = (const float*)d_in[14];
    float* out = (float*)d_out;

    h16 *obs_h, *obs_l, *gw1h, *gw1l, *gw2h, *gw2l;
    h16 *ew1h, *ew2h, *ew3h;
    h16 *g1h, *g1l, *h1, *h2, *h3;
    float *pg2;
    cudaGetSymbolAddress((void**)&obs_h, g_obs_h); cudaGetSymbolAddress((void**)&obs_l, g_obs_l);
    cudaGetSymbolAddress((void**)&gw1h, g_gw1h);   cudaGetSymbolAddress((void**)&gw1l, g_gw1l);
    cudaGetSymbolAddress((void**)&gw2h, g_gw2h);   cudaGetSymbolAddress((void**)&gw2l, g_gw2l);
    cudaGetSymbolAddress((void**)&ew1h, g_ew1h);
    cudaGetSymbolAddress((void**)&ew2h, g_ew2h);
    cudaGetSymbolAddress((void**)&ew3h, g_ew3h);
    cudaGetSymbolAddress((void**)&g1h, g_g1h);     cudaGetSymbolAddress((void**)&g1l, g_g1l);
    cudaGetSymbolAddress((void**)&h1, g_h1);
    cudaGetSymbolAddress((void**)&h2, g_h2);
    cudaGetSymbolAddress((void**)&h3, g_h3);
    cudaGetSymbolAddress((void**)&pg2, g_g2);

    cudaFuncSetAttribute(mma_gemm<false,false,3,1>, cudaFuncAttributeMaxDynamicSharedMemorySize, SMEM3);
    cudaFuncSetAttribute(mma_gemm<false,false,3,2>, cudaFuncAttributeMaxDynamicSharedMemorySize, SMEM3);
    cudaFuncSetAttribute(mma_gemm<true ,true ,1,0>, cudaFuncAttributeMaxDynamicSharedMemorySize, SMEM1);
    cudaFuncSetAttribute(mma_gemm<true ,false,1,0>, cudaFuncAttributeMaxDynamicSharedMemorySize, SMEM1);

    cudaMemsetAsync(out, 0, (size_t)out_size * sizeof(float));

    // fused splits (also zeroes counters)
    SplitArgs sa;
    unsigned n0 = BB*DOBS/4, n1 = DOBS*G1/4, n2 = G1*G2/4;
    unsigned n3 = NE*DOBS*E1/4, n4 = NE*E1*E2/4, n5 = NE*E2*E3/4;
    sa.x[0]=(const float4*)obs; sa.hi[0]=(__half2*)obs_h; sa.lo[0]=(__half2*)obs_l;
    sa.x[1]=(const float4*)gw1; sa.hi[1]=(__half2*)gw1h;  sa.lo[1]=(__half2*)gw1l;
    sa.x[2]=(const float4*)gw2; sa.hi[2]=(__half2*)gw2h;  sa.lo[2]=(__half2*)gw2l;
    sa.x[3]=(const float4*)ew1; sa.hi[3]=(__half2*)ew1h;  sa.lo[3]=nullptr;
    sa.x[4]=(const float4*)ew2; sa.hi[4]=(__half2*)ew2h;  sa.lo[4]=nullptr;
    sa.x[5]=(const float4*)ew3; sa.hi[5]=(__half2*)ew3h;  sa.lo[5]=nullptr;
    sa.end[0]=n0; sa.end[1]=n0+n1; sa.end[2]=n0+n1+n2;
    sa.end[3]=sa.end[2]+n3; sa.end[4]=sa.end[3]+n4; sa.end[5]=sa.end[4]+n5;
    split_all_kernel<<<(sa.end[5] + 255)/256, 256>>>(sa);

    // gating MLP: 3-pass exact (grid transposed: x = n-tiles, y = row tiles)
    mma_gemm<false,false,3,1><<<dim3(G1/128, BB/128), 256, SMEM3>>>(
        obs_h, obs_l, gw1h, gw1l, gb1, g1h, g1l, nullptr, BB, DOBS, G1);
    mma_gemm<false,false,3,2><<<dim3(G2/128, BB/128), 256, SMEM3>>>(
        g1h, g1l, gw2h, gw2l, gb2, nullptr, nullptr, pg2, BB, G1, G2);
    gate_topk_kernel<<<BB/256, 256>>>(gw3, gb3);
    offsets_kernel<<<1, 32>>>();
    scatter_kernel<<<BB/256, 256>>>();

    // grouped expert layers: single-pass fp16 (grid transposed)
    const int T128 = NP/128 + NE;   // 264
    mma_gemm<true,true ,1,0><<<dim3(E1/128, T128), 256, SMEM1>>>(
        obs_h, nullptr, ew1h, nullptr, eb1, h1, nullptr, nullptr, 0, DOBS, E1);
    mma_gemm<true,false,1,0><<<dim3(E2/128, T128), 256, SMEM1>>>(
        h1, nullptr, ew2h, nullptr, eb2, h2, nullptr, nullptr, 0, E1, E2);
    mma_gemm<true,false,1,0><<<dim3(E3/128, T128), 256, SMEM1>>>(
        h2, nullptr, ew3h, nullptr, eb3, h3, nullptr, nullptr, 0, E2, E3);

    // layer 4 + weighted combine
    l4_combine_kernel<<<T128, 256>>>(ew4, eb4, out);
}

// round 14
// speedup vs baseline: 1.2381x; 1.0133x over previous
#include <cuda_runtime.h>
#include <cuda_fp16.h>
#include <cstdint>

#define BB   16384
#define DOBS 512
#define NE   8
#define NA   32
#define G1   256
#define G2   128
#define E1   1024
#define E2   512
#define E3   256
#define NP   (2*BB)

typedef __half h16;

// ---------------- scratch ----------------
__device__ __align__(16) h16 g_obs_h[BB*DOBS], g_obs_l[BB*DOBS];
__device__ __align__(16) h16 g_gw1h[DOBS*G1], g_gw1l[DOBS*G1];
__device__ __align__(16) h16 g_gw2h[G1*G2],   g_gw2l[G1*G2];
__device__ __align__(16) h16 g_ew1h[NE*DOBS*E1];
__device__ __align__(16) h16 g_ew2h[NE*E1*E2];
__device__ __align__(16) h16 g_ew3h[NE*E2*E3];

__device__ __align__(16) h16 g_g1h[BB*G1], g_g1l[BB*G1];
__device__ __align__(16) float g_g2[BB*G2];
__device__ __align__(16) h16 g_h1[(size_t)NP*E1];
__device__ __align__(16) h16 g_h2[(size_t)NP*E2];
__device__ __align__(16) h16 g_h3[(size_t)NP*E3];

__device__ int   g_tidx[BB*2];
__device__ float g_tw[BB*2];
__device__ int   g_counts[NE];
__device__ int   g_off[NE+1];
__device__ int   g_tile128[NE+1];
__device__ int   g_cursor[NE];
__device__ int   g_tok[NP];
__device__ float g_wt[NP];

__device__ __forceinline__ float eluf(float x) { return x > 0.f ? x : expm1f(x); }

// ---------------- PTX helpers ----------------
__device__ __forceinline__ void mma_f16(float* c, const unsigned* a, const unsigned* b) {
    asm volatile(
        "mma.sync.aligned.m16n8k16.row.col.f32.f16.f16.f32 "
        "{%0,%1,%2,%3}, {%4,%5,%6,%7}, {%8,%9}, {%0,%1,%2,%3};"
        : "+f"(c[0]), "+f"(c[1]), "+f"(c[2]), "+f"(c[3])
        : "r"(a[0]), "r"(a[1]), "r"(a[2]), "r"(a[3]), "r"(b[0]), "r"(b[1]));
}
__device__ __forceinline__ void ldsm_x4(unsigned* r, unsigned addr) {
    asm volatile("ldmatrix.sync.aligned.m8n8.x4.shared.b16 {%0,%1,%2,%3}, [%4];"
                 : "=r"(r[0]), "=r"(r[1]), "=r"(r[2]), "=r"(r[3]) : "r"(addr));
}
__device__ __forceinline__ void ldsm_x4_t(unsigned* r, unsigned addr) {
    asm volatile("ldmatrix.sync.aligned.m8n8.x4.trans.shared.b16 {%0,%1,%2,%3}, [%4];"
                 : "=r"(r[0]), "=r"(r[1]), "=r"(r[2]), "=r"(r[3]) : "r"(addr));
}
__device__ __forceinline__ uint32_t s2u(const void* p) {
    uint32_t a;
    asm("{ .reg .u64 t; cvta.to.shared.u64 t, %1; cvt.u32.u64 %0, t; }" : "=r"(a) : "l"(p));
    return a;
}
__device__ __forceinline__ void cpa16(uint32_t dst, const void* src, uint32_t sz) {
    asm volatile("cp.async.cg.shared.global [%0], [%1], 16, %2;" :: "r"(dst), "l"(src), "r"(sz) : "memory");
}
__device__ __forceinline__ void cpcommit() { asm volatile("cp.async.commit_group;" ::: "memory"); }
template<int N> __device__ __forceinline__ void cpwait() { asm volatile("cp.async.wait_group %0;" :: "n"(N) : "memory"); }

// ---------------- fused split ----------------
struct SplitArgs {
    const float4* x[6];
    __half2*      hi[6];
    __half2*      lo[6];
    unsigned      end[6];
};

__global__ __launch_bounds__(256)
void split_all_kernel(SplitArgs a)
{
    if (blockIdx.x == 0 && threadIdx.x < NE) {
        g_counts[threadIdx.x] = 0;
        g_cursor[threadIdx.x] = 0;
    }
    unsigned i = blockIdx.x * 256 + threadIdx.x;
    if (i >= a.end[5]) return;
    int s = 0;
    while (i >= a.end[s]) s++;
    unsigned base = s ? a.end[s-1] : 0;
    unsigned j = i - base;
    float4 v = a.x[s][j];
    h16 h0 = __float2half_rn(v.x), h1 = __float2half_rn(v.y);
    h16 h2 = __float2half_rn(v.z), h3 = __float2half_rn(v.w);
    a.hi[s][2*j]   = __halves2half2(h0, h1);
    a.hi[s][2*j+1] = __halves2half2(h2, h3);
    if (a.lo[s]) {
        a.lo[s][2*j]   = __halves2half2(__float2half_rn(v.x - __half2float(h0)),
                                        __float2half_rn(v.y - __half2float(h1)));
        a.lo[s][2*j+1] = __halves2half2(__float2half_rn(v.z - __half2float(h2)),
                                        __float2half_rn(v.w - __half2float(h3)));
    }
}

// ---------------- pipelined fp16 TC grouped GEMM (128x128, BK=32, NSTG stages) ----------------
// Grid: x = n-tile (fast), y = row tile (grouped for experts).
// NPASS==3 (gating): C = Ah@Bh + Ah@Bl + Al@Bh  |  NPASS==1 (experts): C = A@Bh
// OUTM: 0 = fp16, 1 = fp16 hi/lo, 2 = fp32
#define A_BYTES 10240   // 128 x 40 halves
#define B_BYTES 8704    // 32 x 136 halves

template<bool GROUPED, bool GATHER, int NPASS, int OUTM, int NSTG>
__global__ __launch_bounds__(256)
void mma_gemm(const h16* __restrict__ Ah, const h16* __restrict__ Al,
              const h16* __restrict__ Wh, const h16* __restrict__ Wl,
              const float* __restrict__ bias,
              h16* __restrict__ Ch, h16* __restrict__ Cl, float* __restrict__ Cf,
              int M, int K, int N)
{
    constexpr bool TRI = (NPASS == 3);
    constexpr uint32_t AL_OFF = A_BYTES;
    constexpr uint32_t BH_OFF = TRI ? 2*A_BYTES : A_BYTES;
    constexpr uint32_t BL_OFF = BH_OFF + B_BYTES;
    constexpr uint32_t STG    = BH_OFF + (TRI ? 2 : 1) * B_BYTES;

    extern __shared__ __align__(128) char sm[];
    int row0, rowEnd;
    if (GROUPED) {
        int bx = blockIdx.y;
        if (bx >= g_tile128[NE]) return;
        int e = 0;
        while (bx >= g_tile128[e+1]) e++;
        row0   = g_off[e] + (bx - g_tile128[e]) * 128;
        rowEnd = g_off[e+1];
        if (row0 >= rowEnd) return;
        Wh   += (size_t)e * K * N;
        if (TRI) Wl += (size_t)e * K * N;
        bias += e * N;
    } else {
        row0   = blockIdx.y * 128;
        rowEnd = M;
    }
    const int n0  = blockIdx.x * 128;
    const int tid = threadIdx.x, lane = tid & 31, wid = tid >> 5;
    const int warpM = wid & 3, warpN = wid >> 2;
    const uint32_t su = s2u(sm);

    const int ar  = tid >> 2;
    const int ach = tid & 3;
    const h16 *pAh[2], *pAl[2];
    uint32_t asz[2];
#pragma unroll
    for (int i = 0; i < 2; i++) {
        int gr = row0 + ar + 64*i;
        bool v = gr < rowEnd;
        asz[i] = v ? 16u : 0u;
        size_t rowIdx = 0;
        if (v) rowIdx = GATHER ? (size_t)g_tok[gr] : (size_t)gr;
        pAh[i] = Ah + rowIdx * K + ach*8;
        if (TRI) pAl[i] = Al + rowIdx * K + ach*8;
    }
    const int br  = tid >> 4;
    const int bch = tid & 15;
    const h16* pBh = Wh + (size_t)br * N + n0 + bch*8;
    const h16* pBl = TRI ? (Wl + (size_t)br * N + n0 + bch*8) : nullptr;

    float acc[2][8][4];
#pragma unroll
    for (int mt = 0; mt < 2; mt++)
#pragma unroll
        for (int nt = 0; nt < 8; nt++)
#pragma unroll
            for (int q = 0; q < 4; q++) acc[mt][nt][q] = 0.f;

    const int S = K >> 5;

    auto LOAD = [&](int t) {
        uint32_t base = su + (uint32_t)(t % NSTG) * STG;
        int kf = t * 32;
#pragma unroll
        for (int i = 0; i < 2; i++) {
            uint32_t d = base + (uint32_t)((ar + 64*i)*80 + ach*16);
            cpa16(d, pAh[i] + kf, asz[i]);
            if (TRI) cpa16(d + AL_OFF, pAl[i] + kf, asz[i]);
        }
#pragma unroll
        for (int i = 0; i < 2; i++) {
            uint32_t d = base + (uint32_t)((br + 16*i)*272 + bch*16);
            cpa16(d + BH_OFF, pBh + (size_t)(kf + 16*i) * N, 16u);
            if (TRI) cpa16(d + BL_OFF, pBl + (size_t)(kf + 16*i) * N, 16u);
        }
        cpcommit();
    };

#pragma unroll
    for (int t = 0; t < NSTG-1; t++) LOAD(t);

    for (int s = 0; s < S; s++) {
        __syncthreads();
        int rem = S - 1 - s;
        if (rem >= NSTG-1) { LOAD(s + NSTG - 1); cpwait<NSTG-1>(); }
        else if (NSTG >= 4 && rem == 2) cpwait<(NSTG >= 4) ? 2 : 0>();
        else if (NSTG >= 3 && rem == 1) cpwait<(NSTG >= 3) ? 1 : 0>();
        else cpwait<0>();
        __syncthreads();

        const uint32_t aBase = su + (uint32_t)(s % NSTG) * STG;
#pragma unroll
        for (int kk = 0; kk < 32; kk += 16) {
            unsigned ah[2][4], al[2][4];
#pragma unroll
            for (int mt = 0; mt < 2; mt++) {
                uint32_t off = (uint32_t)(((warpM*32 + mt*16 + (lane & 15))*40 + kk + 8*(lane >> 4)) * 2);
                ldsm_x4(ah[mt], aBase + off);
                if (TRI) ldsm_x4(al[mt], aBase + AL_OFF + off);
            }
            const int brow = kk + (lane & 15);
#pragma unroll
            for (int np = 0; np < 4; np++) {
                const int bcol = warpN*64 + np*16 + 8*(lane >> 4);
                uint32_t boff = (uint32_t)((brow*136 + bcol) * 2);
                unsigned bh[4], bl[4];
                ldsm_x4_t(bh, aBase + BH_OFF + boff);
                if (TRI) ldsm_x4_t(bl, aBase + BL_OFF + boff);
#pragma unroll
                for (int mt = 0; mt < 2; mt++) {
                    mma_f16(acc[mt][2*np],   ah[mt], bh);
                    mma_f16(acc[mt][2*np+1], ah[mt], bh+2);
                    if (TRI) {
                        mma_f16(acc[mt][2*np],   ah[mt], bl);
                        mma_f16(acc[mt][2*np+1], ah[mt], bl+2);
                        mma_f16(acc[mt][2*np],   al[mt], bh);
                        mma_f16(acc[mt][2*np+1], al[mt], bh+2);
                    }
                }
            }
        }
    }

    // ---------------- epilogue ----------------
#pragma unroll
    for (int mt = 0; mt < 2; mt++) {
        int r0 = row0 + warpM*32 + mt*16 + (lane >> 2);
#pragma unroll
        for (int nt = 0; nt < 8; nt++) {
            int c = n0 + warpN*64 + nt*8 + 2*(lane & 3);
            float b0 = __ldg(bias + c), b1 = __ldg(bias + c + 1);
            float v00 = eluf(acc[mt][nt][0] + b0);
            float v01 = eluf(acc[mt][nt][1] + b1);
            float v10 = eluf(acc[mt][nt][2] + b0);
            float v11 = eluf(acc[mt][nt][3] + b1);
#pragma unroll
            for (int rr = 0; rr < 2; rr++) {
                int r = r0 + rr*8;
                float va = rr ? v10 : v00, vb = rr ? v11 : v01;
                if (r < rowEnd) {
                    if (OUTM == 0) {
                        *(__half2*)(Ch + (size_t)r*N + c) =
                            __halves2half2(__float2half_rn(va), __float2half_rn(vb));
                    } else if (OUTM == 1) {
                        h16 h0 = __float2half_rn(va), h1 = __float2half_rn(vb);
                        *(__half2*)(Ch + (size_t)r*N + c) = __halves2half2(h0, h1);
                        *(__half2*)(Cl + (size_t)r*N + c) =
                            __halves2half2(__float2half_rn(va - __half2float(h0)),
                                           __float2half_rn(vb - __half2float(h1)));
                    } else {
                        *(float2*)(Cf + (size_t)r*N + c) = make_float2(va, vb);
                    }
                }
            }
        }
    }
}

// ---------------- gating head: one thread per token ----------------
__global__ __launch_bounds__(256)
void gate_topk_kernel(const float* __restrict__ gw3, const float* __restrict__ gb3)
{
    __shared__ float sW[G2*NE];
    __shared__ float sB[NE];
    const int tid = threadIdx.x;
    for (int i = tid; i < G2*NE; i += 256) sW[i] = gw3[i];
    if (tid < NE) sB[tid] = gb3[tid];
    __syncthreads();

    const int b = blockIdx.x * 256 + tid;
    const float4* g = (const float4*)(g_g2 + (size_t)b * G2);
    float lg[NE];
#pragma unroll
    for (int j = 0; j < NE; j++) lg[j] = sB[j];
#pragma unroll 4
    for (int k4 = 0; k4 < G2/4; k4++) {
        float4 v = g[k4];
        const float* w = sW + k4*4*NE;
#pragma unroll
        for (int j = 0; j < NE; j++)
            lg[j] += v.x*w[j] + v.y*w[NE+j] + v.z*w[2*NE+j] + v.w*w[3*NE+j];
    }
    int i0 = 0; float m0 = lg[0];
#pragma unroll
    for (int j = 1; j < NE; j++) if (lg[j] > m0) { m0 = lg[j]; i0 = j; }
    int i1 = -1; float m1 = -3.4e38f;
#pragma unroll
    for (int j = 0; j < NE; j++) if (j != i0 && lg[j] > m1) { m1 = lg[j]; i1 = j; }
    float e1  = expf(m1 - m0);
    float inv = 1.f / (1.f + e1);
    g_tidx[b*2+0] = i0; g_tidx[b*2+1] = i1;
    g_tw[b*2+0] = inv;  g_tw[b*2+1] = e1 * inv;
    atomicAdd(&g_counts[i0], 1);
    atomicAdd(&g_counts[i1], 1);
}

// ---------------- prefix sums ----------------
__global__ void offsets_kernel()
{
    if (threadIdx.x == 0 && blockIdx.x == 0) {
        int o = 0, t128 = 0;
        for (int e = 0; e < NE; e++) {
            g_off[e] = o; g_tile128[e] = t128;
            int c = g_counts[e];
            o += c; t128 += (c + 127) >> 7;
        }
        g_off[NE] = o; g_tile128[NE] = t128;
    }
}

// ---------------- scatter ----------------
__global__ __launch_bounds__(256)
void scatter_kernel()
{
    const int b    = blockIdx.x * 256 + threadIdx.x;
    const int lane = threadIdx.x & 31;
#pragma unroll
    for (int s = 0; s < 2; s++) {
        int   e = g_tidx[b*2 + s];
        float w = g_tw[b*2 + s];
#pragma unroll
        for (int ee = 0; ee < NE; ee++) {
            unsigned m = __ballot_sync(0xffffffffu, e == ee);
            if (e == ee) {
                int rank   = __popc(m & ((1u << lane) - 1u));
                int leader = __ffs(m) - 1;
                int base = 0;
                if (lane == leader) base = atomicAdd(&g_cursor[ee], __popc(m));
                base = __shfl_sync(m, base, leader);
                int p = g_off[ee] + base + rank;
                g_tok[p] = b; g_wt[p] = w;
            }
        }
    }
}

// ---------------- layer 4 (K=256, N=32) + weighted combine, 128 rows/block ----------------
__global__ __launch_bounds__(256)
void l4_combine_kernel(const float* __restrict__ W4, const float* __restrict__ B4,
                       float* __restrict__ out)
{
    const int bx = blockIdx.x;
    if (bx >= g_tile128[NE]) return;
    int e = 0;
    while (bx >= g_tile128[e+1]) e++;
    const int row0   = g_off[e] + (bx - g_tile128[e]) * 128;
    const int rowEnd = g_off[e+1];

    __shared__ float sW[E3*NA];
    const float* We = W4 + (size_t)e * E3 * NA;
    for (int i = threadIdx.x; i < E3*NA/4; i += 256)
        *(float4*)&sW[i*4] = *(const float4*)&We[i*4];
    __syncthreads();

    const int r  = threadIdx.x >> 3;
    const int c4 = (threadIdx.x & 7) * 4;
    const float bb0 = B4[e*NA + c4 + 0], bb1 = B4[e*NA + c4 + 1];
    const float bb2 = B4[e*NA + c4 + 2], bb3 = B4[e*NA + c4 + 3];

#pragma unroll
    for (int it = 0; it < 4; it++) {
        const int row = row0 + r + 32*it;
        if (row >= rowEnd) break;
        const __half2* hh = (const __half2*)(g_h3 + (size_t)row * E3);
        float a0 = 0.f, a1 = 0.f, a2 = 0.f, a3 = 0.f;
#pragma unroll 4
        for (int k = 0; k < E3; k += 4) {
            float2 p0 = __half22float2(hh[k/2]);
            float2 p1 = __half22float2(hh[k/2+1]);
            float4 w0 = *(float4*)&sW[(k+0)*NA + c4];
            float4 w1 = *(float4*)&sW[(k+1)*NA + c4];
            float4 w2 = *(float4*)&sW[(k+2)*NA + c4];
            float4 w3 = *(float4*)&sW[(k+3)*NA + c4];
            a0 += p0.x*w0.x + p0.y*w1.x + p1.x*w2.x + p1.y*w3.x;
            a1 += p0.x*w0.y + p0.y*w1.y + p1.x*w2.y + p1.y*w3.y;
            a2 += p0.x*w0.z + p0.y*w1.z + p1.x*w2.z + p1.y*w3.z;
            a3 += p0.x*w0.w + p0.y*w1.w + p1.x*w2.w + p1.y*w3.w;
        }
        const int   tok = g_tok[row];
        const float w   = g_wt[row];
        float* o = out + (size_t)tok * NA + c4;
        atomicAdd(o+0, w*(a0 + bb0));
        atomicAdd(o+1, w*(a1 + bb1));
        atomicAdd(o+2, w*(a2 + bb2));
        atomicAdd(o+3, w*(a3 + bb3));
    }
}

// ---------------- launch ----------------
#define SMEMG (2 * (2*A_BYTES + 2*B_BYTES))   // 75776 (gating, 2-stage, 2 CTAs/SM)
#define SMEME (4 * (A_BYTES + B_BYTES))       // 75776 (experts, 4-stage, 2 CTAs/SM)

extern "C" void kernel_launch(void* const* d_in, const int* in_sizes, int n_in,
                              void* d_out, int out_size)
{
    const float* obs = (const float*)d_in[0];
    const float* gw1 = (const float*)d_in[1];
    const float* gb1 = (const float*)d_in[2];
    const float* gw2 = (const float*)d_in[3];
    const float* gb2 = (const float*)d_in[4];
    const float* gw3 = (const float*)d_in[5];
    const float* gb3 = (const float*)d_in[6];
    const float* ew1 = (const float*)d_in[7];
    const float* eb1 = (const float*)d_in[8];
    const float* ew2 = (const float*)d_in[9];
    const float* eb2 = (const float*)d_in[10];
    const float* ew3 = (const float*)d_in[11];
    const float* eb3 = (const float*)d_in[12];
    const float* ew4 = (const float*)d_in[13];
    const float* eb4 = (const float*)d_in[14];
    float* out = (float*)d_out;

    h16 *obs_h, *obs_l, *gw1h, *gw1l, *gw2h, *gw2l;
    h16 *ew1h, *ew2h, *ew3h;
    h16 *g1h, *g1l, *h1, *h2, *h3;
    float *pg2;
    cudaGetSymbolAddress((void**)&obs_h, g_obs_h); cudaGetSymbolAddress((void**)&obs_l, g_obs_l);
    cudaGetSymbolAddress((void**)&gw1h, g_gw1h);   cudaGetSymbolAddress((void**)&gw1l, g_gw1l);
    cudaGetSymbolAddress((void**)&gw2h, g_gw2h);   cudaGetSymbolAddress((void**)&gw2l, g_gw2l);
    cudaGetSymbolAddress((void**)&ew1h, g_ew1h);
    cudaGetSymbolAddress((void**)&ew2h, g_ew2h);
    cudaGetSymbolAddress((void**)&ew3h, g_ew3h);
    cudaGetSymbolAddress((void**)&g1h, g_g1h);     cudaGetSymbolAddress((void**)&g1l, g_g1l);
    cudaGetSymbolAddress((void**)&h1, g_h1);
    cudaGetSymbolAddress((void**)&h2, g_h2);
    cudaGetSymbolAddress((void**)&h3, g_h3);
    cudaGetSymbolAddress((void**)&pg2, g_g2);

    cudaFuncSetAttribute(mma_gemm<false,false,3,1,2>, cudaFuncAttributeMaxDynamicSharedMemorySize, SMEMG);
    cudaFuncSetAttribute(mma_gemm<false,false,3,2,2>, cudaFuncAttributeMaxDynamicSharedMemorySize, SMEMG);
    cudaFuncSetAttribute(mma_gemm<true ,true ,1,0,4>, cudaFuncAttributeMaxDynamicSharedMemorySize, SMEME);
    cudaFuncSetAttribute(mma_gemm<true ,false,1,0,4>, cudaFuncAttributeMaxDynamicSharedMemorySize, SMEME);

    cudaMemsetAsync(out, 0, (size_t)out_size * sizeof(float));

    // fused splits (also zeroes counters)
    SplitArgs sa;
    unsigned n0 = BB*DOBS/4, n1 = DOBS*G1/4, n2 = G1*G2/4;
    unsigned n3 = NE*DOBS*E1/4, n4 = NE*E1*E2/4, n5 = NE*E2*E3/4;
    sa.x[0]=(const float4*)obs; sa.hi[0]=(__half2*)obs_h; sa.lo[0]=(__half2*)obs_l;
    sa.x[1]=(const float4*)gw1; sa.hi[1]=(__half2*)gw1h;  sa.lo[1]=(__half2*)gw1l;
    sa.x[2]=(const float4*)gw2; sa.hi[2]=(__half2*)gw2h;  sa.lo[2]=(__half2*)gw2l;
    sa.x[3]=(const float4*)ew1; sa.hi[3]=(__half2*)ew1h;  sa.lo[3]=nullptr;
    sa.x[4]=(const float4*)ew2; sa.hi[4]=(__half2*)ew2h;  sa.lo[4]=nullptr;
    sa.x[5]=(const float4*)ew3; sa.hi[5]=(__half2*)ew3h;  sa.lo[5]=nullptr;
    sa.end[0]=n0; sa.end[1]=n0+n1; sa.end[2]=n0+n1+n2;
    sa.end[3]=sa.end[2]+n3; sa.end[4]=sa.end[3]+n4; sa.end[5]=sa.end[4]+n5;
    split_all_kernel<<<(sa.end[5] + 255)/256, 256>>>(sa);

    // gating MLP: 3-pass exact, 2-stage / 2 CTAs per SM
    mma_gemm<false,false,3,1,2><<<dim3(G1/128, BB/128), 256, SMEMG>>>(
        obs_h, obs_l, gw1h, gw1l, gb1, g1h, g1l, nullptr, BB, DOBS, G1);
    mma_gemm<false,false,3,2,2><<<dim3(G2/128, BB/128), 256, SMEMG>>>(
        g1h, g1l, gw2h, gw2l, gb2, nullptr, nullptr, pg2, BB, G1, G2);
    gate_topk_kernel<<<BB/256, 256>>>(gw3, gb3);
    offsets_kernel<<<1, 32>>>();
    scatter_kernel<<<BB/256, 256>>>();

    // grouped expert layers: single-pass fp16, 4-stage / 2 CTAs per SM
    const int T128 = NP/128 + NE;   // 264
    mma_gemm<true,true ,1,0,4><<<dim3(E1/128, T128), 256, SMEME>>>(
        obs_h, nullptr, ew1h, nullptr, eb1, h1, nullptr, nullptr, 0, DOBS, E1);
    mma_gemm<true,false,1,0,4><<<dim3(E2/128, T128), 256, SMEME>>>(
        h1, nullptr, ew2h, nullptr, eb2, h2, nullptr, nullptr, 0, E1, E2);
    mma_gemm<true,false,1,0,4><<<dim3(E3/128, T128), 256, SMEME>>>(
        h2, nullptr, ew3h, nullptr, eb3, h3, nullptr, nullptr, 0, E2, E3);

    // layer 4 + weighted combine
    l4_combine_kernel<<<T128, 256>>>(ew4, eb4, out);
}

// round 15
// speedup vs baseline: 1.2520x; 1.0112x over previous
#include <cuda_runtime.h>
#include <cuda_fp16.h>
#include <cstdint>

#define BB   16384
#define DOBS 512
#define NE   8
#define NA   32
#define G1   256
#define G2   128
#define E1   1024
#define E2   512
#define E3   256
#define NP   (2*BB)

typedef __half h16;

// ---------------- scratch ----------------
__device__ __align__(16) h16 g_obs_h[BB*DOBS], g_obs_l[BB*DOBS];
__device__ __align__(16) h16 g_gw1h[DOBS*G1], g_gw1l[DOBS*G1];
__device__ __align__(16) h16 g_gw2h[G1*G2],   g_gw2l[G1*G2];
__device__ __align__(16) h16 g_ew1h[NE*DOBS*E1];
__device__ __align__(16) h16 g_ew2h[NE*E1*E2];
__device__ __align__(16) h16 g_ew3h[NE*E2*E3];

__device__ __align__(16) h16 g_g1h[BB*G1], g_g1l[BB*G1];
__device__ __align__(16) h16 g_h1[(size_t)NP*E1];
__device__ __align__(16) h16 g_h2[(size_t)NP*E2];
__device__ __align__(16) h16 g_h3[(size_t)NP*E3];

__device__ int   g_tidx[BB*2];
__device__ float g_tw[BB*2];
__device__ int   g_counts[NE];
__device__ int   g_off[NE+1];
__device__ int   g_tile128[NE+1];
__device__ int   g_cursor[NE];
__device__ int   g_tok[NP];
__device__ float g_wt[NP];

__device__ __forceinline__ float eluf(float x) { return x > 0.f ? x : expm1f(x); }

// ---------------- PTX helpers ----------------
__device__ __forceinline__ void mma_f16(float* c, const unsigned* a, const unsigned* b) {
    asm volatile(
        "mma.sync.aligned.m16n8k16.row.col.f32.f16.f16.f32 "
        "{%0,%1,%2,%3}, {%4,%5,%6,%7}, {%8,%9}, {%0,%1,%2,%3};"
        : "+f"(c[0]), "+f"(c[1]), "+f"(c[2]), "+f"(c[3])
        : "r"(a[0]), "r"(a[1]), "r"(a[2]), "r"(a[3]), "r"(b[0]), "r"(b[1]));
}
__device__ __forceinline__ void ldsm_x4(unsigned* r, unsigned addr) {
    asm volatile("ldmatrix.sync.aligned.m8n8.x4.shared.b16 {%0,%1,%2,%3}, [%4];"
                 : "=r"(r[0]), "=r"(r[1]), "=r"(r[2]), "=r"(r[3]) : "r"(addr));
}
__device__ __forceinline__ void ldsm_x4_t(unsigned* r, unsigned addr) {
    asm volatile("ldmatrix.sync.aligned.m8n8.x4.trans.shared.b16 {%0,%1,%2,%3}, [%4];"
                 : "=r"(r[0]), "=r"(r[1]), "=r"(r[2]), "=r"(r[3]) : "r"(addr));
}
__device__ __forceinline__ uint32_t s2u(const void* p) {
    uint32_t a;
    asm("{ .reg .u64 t; cvta.to.shared.u64 t, %1; cvt.u32.u64 %0, t; }" : "=r"(a) : "l"(p));
    return a;
}
__device__ __forceinline__ void cpa16(uint32_t dst, const void* src, uint32_t sz) {
    asm volatile("cp.async.cg.shared.global [%0], [%1], 16, %2;" :: "r"(dst), "l"(src), "r"(sz) : "memory");
}
__device__ __forceinline__ void cpcommit() { asm volatile("cp.async.commit_group;" ::: "memory"); }
template<int N> __device__ __forceinline__ void cpwait() { asm volatile("cp.async.wait_group %0;" :: "n"(N) : "memory"); }

// ---------------- fused split ----------------
struct SplitArgs {
    const float4* x[6];
    __half2*      hi[6];
    __half2*      lo[6];
    unsigned      end[6];
};

__global__ __launch_bounds__(256)
void split_all_kernel(SplitArgs a)
{
    if (blockIdx.x == 0 && threadIdx.x < NE) {
        g_counts[threadIdx.x] = 0;
        g_cursor[threadIdx.x] = 0;
    }
    unsigned i = blockIdx.x * 256 + threadIdx.x;
    if (i >= a.end[5]) return;
    int s = 0;
    while (i >= a.end[s]) s++;
    unsigned base = s ? a.end[s-1] : 0;
    unsigned j = i - base;
    float4 v = a.x[s][j];
    h16 h0 = __float2half_rn(v.x), h1 = __float2half_rn(v.y);
    h16 h2 = __float2half_rn(v.z), h3 = __float2half_rn(v.w);
    a.hi[s][2*j]   = __halves2half2(h0, h1);
    a.hi[s][2*j+1] = __halves2half2(h2, h3);
    if (a.lo[s]) {
        a.lo[s][2*j]   = __halves2half2(__float2half_rn(v.x - __half2float(h0)),
                                        __float2half_rn(v.y - __half2float(h1)));
        a.lo[s][2*j+1] = __halves2half2(__float2half_rn(v.z - __half2float(h2)),
                                        __float2half_rn(v.w - __half2float(h3)));
    }
}

// ---------------- pipelined fp16 TC grouped GEMM (128x128, BK=32, NSTG stages) ----------------
// Grid: x = n-tile (fast), y = row tile (grouped for experts).
// NPASS==3 (gating): C = Ah@Bh + Ah@Bl + Al@Bh  |  NPASS==1 (experts): C = A@Bh
// OUTM: 0 = fp16, 1 = fp16 hi/lo, 3 = fused topk (gate2: bias+ELU -> smem -> logits+top2+counts)
#define A_BYTES 10240   // 128 x 40 halves
#define B_BYTES 8704    // 32 x 136 halves

template<bool GROUPED, bool GATHER, int NPASS, int OUTM, int NSTG>
__global__ __launch_bounds__(256)
void mma_gemm(const h16* __restrict__ Ah, const h16* __restrict__ Al,
              const h16* __restrict__ Wh, const h16* __restrict__ Wl,
              const float* __restrict__ bias,
              h16* __restrict__ Ch, h16* __restrict__ Cl,
              const float* __restrict__ gw3, const float* __restrict__ gb3,
              int M, int K, int N)
{
    constexpr bool TRI = (NPASS == 3);
    constexpr uint32_t AL_OFF = A_BYTES;
    constexpr uint32_t BH_OFF = TRI ? 2*A_BYTES : A_BYTES;
    constexpr uint32_t BL_OFF = BH_OFF + B_BYTES;
    constexpr uint32_t STG    = BH_OFF + (TRI ? 2 : 1) * B_BYTES;

    extern __shared__ __align__(128) char sm[];
    int row0, rowEnd;
    if (GROUPED) {
        int bx = blockIdx.y;
        if (bx >= g_tile128[NE]) return;
        int e = 0;
        while (bx >= g_tile128[e+1]) e++;
        row0   = g_off[e] + (bx - g_tile128[e]) * 128;
        rowEnd = g_off[e+1];
        if (row0 >= rowEnd) return;
        Wh   += (size_t)e * K * N;
        if (TRI) Wl += (size_t)e * K * N;
        bias += e * N;
    } else {
        row0   = blockIdx.y * 128;
        rowEnd = M;
    }
    const int n0  = blockIdx.x * 128;
    const int tid = threadIdx.x, lane = tid & 31, wid = tid >> 5;
    const int warpM = wid & 3, warpN = wid >> 2;
    const uint32_t su = s2u(sm);

    const int ar  = tid >> 2;
    const int ach = tid & 3;
    const h16 *pAh[2], *pAl[2];
    uint32_t asz[2];
#pragma unroll
    for (int i = 0; i < 2; i++) {
        int gr = row0 + ar + 64*i;
        bool v = gr < rowEnd;
        asz[i] = v ? 16u : 0u;
        size_t rowIdx = 0;
        if (v) rowIdx = GATHER ? (size_t)g_tok[gr] : (size_t)gr;
        pAh[i] = Ah + rowIdx * K + ach*8;
        if (TRI) pAl[i] = Al + rowIdx * K + ach*8;
    }
    const int br  = tid >> 4;
    const int bch = tid & 15;
    const h16* pBh = Wh + (size_t)br * N + n0 + bch*8;
    const h16* pBl = TRI ? (Wl + (size_t)br * N + n0 + bch*8) : nullptr;

    float acc[2][8][4];
#pragma unroll
    for (int mt = 0; mt < 2; mt++)
#pragma unroll
        for (int nt = 0; nt < 8; nt++)
#pragma unroll
            for (int q = 0; q < 4; q++) acc[mt][nt][q] = 0.f;

    const int S = K >> 5;

    auto LOAD = [&](int t) {
        uint32_t base = su + (uint32_t)(t % NSTG) * STG;
        int kf = t * 32;
#pragma unroll
        for (int i = 0; i < 2; i++) {
            uint32_t d = base + (uint32_t)((ar + 64*i)*80 + ach*16);
            cpa16(d, pAh[i] + kf, asz[i]);
            if (TRI) cpa16(d + AL_OFF, pAl[i] + kf, asz[i]);
        }
#pragma unroll
        for (int i = 0; i < 2; i++) {
            uint32_t d = base + (uint32_t)((br + 16*i)*272 + bch*16);
            cpa16(d + BH_OFF, pBh + (size_t)(kf + 16*i) * N, 16u);
            if (TRI) cpa16(d + BL_OFF, pBl + (size_t)(kf + 16*i) * N, 16u);
        }
        cpcommit();
    };

#pragma unroll
    for (int t = 0; t < NSTG-1; t++) LOAD(t);

    for (int s = 0; s < S; s++) {
        __syncthreads();
        int rem = S - 1 - s;
        if (rem >= NSTG-1) { LOAD(s + NSTG - 1); cpwait<NSTG-1>(); }
        else if (NSTG >= 4 && rem == 2) cpwait<(NSTG >= 4) ? 2 : 0>();
        else if (NSTG >= 3 && rem == 1) cpwait<(NSTG >= 3) ? 1 : 0>();
        else cpwait<0>();
        __syncthreads();

        const uint32_t aBase = su + (uint32_t)(s % NSTG) * STG;
#pragma unroll
        for (int kk = 0; kk < 32; kk += 16) {
            unsigned ah[2][4], al[2][4];
#pragma unroll
            for (int mt = 0; mt < 2; mt++) {
                uint32_t off = (uint32_t)(((warpM*32 + mt*16 + (lane & 15))*40 + kk + 8*(lane >> 4)) * 2);
                ldsm_x4(ah[mt], aBase + off);
                if (TRI) ldsm_x4(al[mt], aBase + AL_OFF + off);
            }
            const int brow = kk + (lane & 15);
#pragma unroll
            for (int np = 0; np < 4; np++) {
                const int bcol = warpN*64 + np*16 + 8*(lane >> 4);
                uint32_t boff = (uint32_t)((brow*136 + bcol) * 2);
                unsigned bh[4], bl[4];
                ldsm_x4_t(bh, aBase + BH_OFF + boff);
                if (TRI) ldsm_x4_t(bl, aBase + BL_OFF + boff);
#pragma unroll
                for (int mt = 0; mt < 2; mt++) {
                    mma_f16(acc[mt][2*np],   ah[mt], bh);
                    mma_f16(acc[mt][2*np+1], ah[mt], bh+2);
                    if (TRI) {
                        mma_f16(acc[mt][2*np],   ah[mt], bl);
                        mma_f16(acc[mt][2*np+1], ah[mt], bl+2);
                        mma_f16(acc[mt][2*np],   al[mt], bh);
                        mma_f16(acc[mt][2*np+1], al[mt], bh+2);
                    }
                }
            }
        }
    }

    // ---------------- epilogue ----------------
    if (OUTM == 3) {
        // gate2 fused path: bias+ELU -> smem [128][132] fp32, then logits + top2 + counts.
        __syncthreads();                   // pipeline smem reuse
        float* sOut = (float*)sm;          // 128*132*4 = 67584 B
        float* sW3  = (float*)(sm + 67584);  // 128*8*4 = 4096 B
        float* sB3  = (float*)(sm + 67584 + 4096);  // 32 B
#pragma unroll
        for (int mt = 0; mt < 2; mt++) {
            int rloc = warpM*32 + mt*16 + (lane >> 2);
#pragma unroll
            for (int nt = 0; nt < 8; nt++) {
                int c = warpN*64 + nt*8 + 2*(lane & 3);
                float b0 = __ldg(bias + c), b1 = __ldg(bias + c + 1);
                sOut[rloc*132 + c]         = eluf(acc[mt][nt][0] + b0);
                sOut[rloc*132 + c + 1]     = eluf(acc[mt][nt][1] + b1);
                sOut[(rloc+8)*132 + c]     = eluf(acc[mt][nt][2] + b0);
                sOut[(rloc+8)*132 + c + 1] = eluf(acc[mt][nt][3] + b1);
            }
        }
        for (int i = tid; i < G2*NE; i += 256) sW3[i] = gw3[i];
        if (tid < NE) sB3[tid] = gb3[tid];
        __syncthreads();

        if (tid < 128) {
            const int b = row0 + tid;
            float lg[NE];
#pragma unroll
            for (int j = 0; j < NE; j++) lg[j] = sB3[j];
#pragma unroll 4
            for (int k4 = 0; k4 < G2/4; k4++) {
                float4 v = *(const float4*)&sOut[tid*132 + k4*4];
                const float* w = sW3 + k4*4*NE;
#pragma unroll
                for (int j = 0; j < NE; j++)
                    lg[j] += v.x*w[j] + v.y*w[NE+j] + v.z*w[2*NE+j] + v.w*w[3*NE+j];
            }
            int i0 = 0; float m0 = lg[0];
#pragma unroll
            for (int j = 1; j < NE; j++) if (lg[j] > m0) { m0 = lg[j]; i0 = j; }
            int i1 = -1; float m1 = -3.4e38f;
#pragma unroll
            for (int j = 0; j < NE; j++) if (j != i0 && lg[j] > m1) { m1 = lg[j]; i1 = j; }
            float e1  = expf(m1 - m0);
            float inv = 1.f / (1.f + e1);
            g_tidx[b*2+0] = i0; g_tidx[b*2+1] = i1;
            g_tw[b*2+0] = inv;  g_tw[b*2+1] = e1 * inv;
            atomicAdd(&g_counts[i0], 1);
            atomicAdd(&g_counts[i1], 1);
        }
        return;
    }

#pragma unroll
    for (int mt = 0; mt < 2; mt++) {
        int r0 = row0 + warpM*32 + mt*16 + (lane >> 2);
#pragma unroll
        for (int nt = 0; nt < 8; nt++) {
            int c = n0 + warpN*64 + nt*8 + 2*(lane & 3);
            float b0 = __ldg(bias + c), b1 = __ldg(bias + c + 1);
            float v00 = eluf(acc[mt][nt][0] + b0);
            float v01 = eluf(acc[mt][nt][1] + b1);
            float v10 = eluf(acc[mt][nt][2] + b0);
            float v11 = eluf(acc[mt][nt][3] + b1);
#pragma unroll
            for (int rr = 0; rr < 2; rr++) {
                int r = r0 + rr*8;
                float va = rr ? v10 : v00, vb = rr ? v11 : v01;
                if (r < rowEnd) {
                    if (OUTM == 0) {
                        *(__half2*)(Ch + (size_t)r*N + c) =
                            __halves2half2(__float2half_rn(va), __float2half_rn(vb));
                    } else {
                        h16 h0 = __float2half_rn(va), h1 = __float2half_rn(vb);
                        *(__half2*)(Ch + (size_t)r*N + c) = __halves2half2(h0, h1);
                        *(__half2*)(Cl + (size_t)r*N + c) =
                            __halves2half2(__float2half_rn(va - __half2float(h0)),
                                           __float2half_rn(vb - __half2float(h1)));
                    }
                }
            }
        }
    }
}

// ---------------- prefix sums ----------------
__global__ void offsets_kernel()
{
    if (threadIdx.x == 0 && blockIdx.x == 0) {
        int o = 0, t128 = 0;
        for (int e = 0; e < NE; e++) {
            g_off[e] = o; g_tile128[e] = t128;
            int c = g_counts[e];
            o += c; t128 += (c + 127) >> 7;
        }
        g_off[NE] = o; g_tile128[NE] = t128;
    }
}

// ---------------- scatter ----------------
__global__ __launch_bounds__(256)
void scatter_kernel()
{
    const int b    = blockIdx.x * 256 + threadIdx.x;
    const int lane = threadIdx.x & 31;
#pragma unroll
    for (int s = 0; s < 2; s++) {
        int   e = g_tidx[b*2 + s];
        float w = g_tw[b*2 + s];
#pragma unroll
        for (int ee = 0; ee < NE; ee++) {
            unsigned m = __ballot_sync(0xffffffffu, e == ee);
            if (e == ee) {
                int rank   = __popc(m & ((1u << lane) - 1u));
                int leader = __ffs(m) - 1;
                int base = 0;
                if (lane == leader) base = atomicAdd(&g_cursor[ee], __popc(m));
                base = __shfl_sync(m, base, leader);
                int p = g_off[ee] + base + rank;
                g_tok[p] = b; g_wt[p] = w;
            }
        }
    }
}

// ---------------- layer 4 (K=256, N=32) + weighted combine, 128 rows/block ----------------
__global__ __launch_bounds__(256)
void l4_combine_kernel(const float* __restrict__ W4, const float* __restrict__ B4,
                       float* __restrict__ out)
{
    const int bx = blockIdx.x;
    if (bx >= g_tile128[NE]) return;
    int e = 0;
    while (bx >= g_tile128[e+1]) e++;
    const int row0   = g_off[e] + (bx - g_tile128[e]) * 128;
    const int rowEnd = g_off[e+1];

    __shared__ float sW[E3*NA];
    const float* We = W4 + (size_t)e * E3 * NA;
    for (int i = threadIdx.x; i < E3*NA/4; i += 256)
        *(float4*)&sW[i*4] = *(const float4*)&We[i*4];
    __syncthreads();

    const int r  = threadIdx.x >> 3;
    const int c4 = (threadIdx.x & 7) * 4;
    const float bb0 = B4[e*NA + c4 + 0], bb1 = B4[e*NA + c4 + 1];
    const float bb2 = B4[e*NA + c4 + 2], bb3 = B4[e*NA + c4 + 3];

#pragma unroll
    for (int it = 0; it < 4; it++) {
        const int row = row0 + r + 32*it;
        if (row >= rowEnd) break;
        const __half2* hh = (const __half2*)(g_h3 + (size_t)row * E3);
        float a0 = 0.f, a1 = 0.f, a2 = 0.f, a3 = 0.f;
#pragma unroll 4
        for (int k = 0; k < E3; k += 4) {
            float2 p0 = __half22float2(hh[k/2]);
            float2 p1 = __half22float2(hh[k/2+1]);
            float4 w0 = *(float4*)&sW[(k+0)*NA + c4];
            float4 w1 = *(float4*)&sW[(k+1)*NA + c4];
            float4 w2 = *(float4*)&sW[(k+2)*NA + c4];
            float4 w3 = *(float4*)&sW[(k+3)*NA + c4];
            a0 += p0.x*w0.x + p0.y*w1.x + p1.x*w2.x + p1.y*w3.x;
            a1 += p0.x*w0.y + p0.y*w1.y + p1.x*w2.y + p1.y*w3.y;
            a2 += p0.x*w0.z + p0.y*w1.z + p1.x*w2.z + p1.y*w3.z;
            a3 += p0.x*w0.w + p0.y*w1.w + p1.x*w2.w + p1.y*w3.w;
        }
        const int   tok = g_tok[row];
        const float w   = g_wt[row];
        float* o = out + (size_t)tok * NA + c4;
        atomicAdd(o+0, w*(a0 + bb0));
        atomicAdd(o+1, w*(a1 + bb1));
        atomicAdd(o+2, w*(a2 + bb2));
        atomicAdd(o+3, w*(a3 + bb3));
    }
}

// ---------------- launch ----------------
#define SMEMG (2 * (2*A_BYTES + 2*B_BYTES))   // 75776 (gating, 2-stage, 2 CTAs/SM)
#define SMEME (4 * (A_BYTES + B_BYTES))       // 75776 (experts, 4-stage, 2 CTAs/SM)

extern "C" void kernel_launch(void* const* d_in, const int* in_sizes, int n_in,
                              void* d_out, int out_size)
{
    const float* obs = (const float*)d_in[0];
    const float* gw1 = (const float*)d_in[1];
    const float* gb1 = (const float*)d_in[2];
    const float* gw2 = (const float*)d_in[3];
    const float* gb2 = (const float*)d_in[4];
    const float* gw3 = (const float*)d_in[5];
    const float* gb3 = (const float*)d_in[6];
    const float* ew1 = (const float*)d_in[7];
    const float* eb1 = (const float*)d_in[8];
    const float* ew2 = (const float*)d_in[9];
    const float* eb2 = (const float*)d_in[10];
    const float* ew3 = (const float*)d_in[11];
    const float* eb3 = (const float*)d_in[12];
    const float* ew4 = (const float*)d_in[13];
    const float* eb4 = (const float*)d_in[14];
    float* out = (float*)d_out;

    h16 *obs_h, *obs_l, *gw1h, *gw1l, *gw2h, *gw2l;
    h16 *ew1h, *ew2h, *ew3h;
    h16 *g1h, *g1l, *h1, *h2, *h3;
    cudaGetSymbolAddress((void**)&obs_h, g_obs_h); cudaGetSymbolAddress((void**)&obs_l, g_obs_l);
    cudaGetSymbolAddress((void**)&gw1h, g_gw1h);   cudaGetSymbolAddress((void**)&gw1l, g_gw1l);
    cudaGetSymbolAddress((void**)&gw2h, g_gw2h);   cudaGetSymbolAddress((void**)&gw2l, g_gw2l);
    cudaGetSymbolAddress((void**)&ew1h, g_ew1h);
    cudaGetSymbolAddress((void**)&ew2h, g_ew2h);
    cudaGetSymbolAddress((void**)&ew3h, g_ew3h);
    cudaGetSymbolAddress((void**)&g1h, g_g1h);     cudaGetSymbolAddress((void**)&g1l, g_g1l);
    cudaGetSymbolAddress((void**)&h1, g_h1);
    cudaGetSymbolAddress((void**)&h2, g_h2);
    cudaGetSymbolAddress((void**)&h3, g_h3);

    cudaFuncSetAttribute(mma_gemm<false,false,3,1,2>, cudaFuncAttributeMaxDynamicSharedMemorySize, SMEMG);
    cudaFuncSetAttribute(mma_gemm<false,false,3,3,2>, cudaFuncAttributeMaxDynamicSharedMemorySize, SMEMG);
    cudaFuncSetAttribute(mma_gemm<true ,true ,1,0,4>, cudaFuncAttributeMaxDynamicSharedMemorySize, SMEME);
    cudaFuncSetAttribute(mma_gemm<true ,false,1,0,4>, cudaFuncAttributeMaxDynamicSharedMemorySize, SMEME);

    cudaMemsetAsync(out, 0, (size_t)out_size * sizeof(float));

    // fused splits (also zeroes counters)
    SplitArgs sa;
    unsigned n0 = BB*DOBS/4, n1 = DOBS*G1/4, n2 = G1*G2/4;
    unsigned n3 = NE*DOBS*E1/4, n4 = NE*E1*E2/4, n5 = NE*E2*E3/4;
    sa.x[0]=(const float4*)obs; sa.hi[0]=(__half2*)obs_h; sa.lo[0]=(__half2*)obs_l;
    sa.x[1]=(const float4*)gw1; sa.hi[1]=(__half2*)gw1h;  sa.lo[1]=(__half2*)gw1l;
    sa.x[2]=(const float4*)gw2; sa.hi[2]=(__half2*)gw2h;  sa.lo[2]=(__half2*)gw2l;
    sa.x[3]=(const float4*)ew1; sa.hi[3]=(__half2*)ew1h;  sa.lo[3]=nullptr;
    sa.x[4]=(const float4*)ew2; sa.hi[4]=(__half2*)ew2h;  sa.lo[4]=nullptr;
    sa.x[5]=(const float4*)ew3; sa.hi[5]=(__half2*)ew3h;  sa.lo[5]=nullptr;
    sa.end[0]=n0; sa.end[1]=n0+n1; sa.end[2]=n0+n1+n2;
    sa.end[3]=sa.end[2]+n3; sa.end[4]=sa.end[3]+n4; sa.end[5]=sa.end[4]+n5;
    split_all_kernel<<<(sa.end[5] + 255)/256, 256>>>(sa);

    // gating MLP: 3-pass exact, 2-stage; gate2 fuses logits+top2+counts
    mma_gemm<false,false,3,1,2><<<dim3(G1/128, BB/128), 256, SMEMG>>>(
        obs_h, obs_l, gw1h, gw1l, gb1, g1h, g1l, nullptr, nullptr, BB, DOBS, G1);
    mma_gemm<false,false,3,3,2><<<dim3(G2/128, BB/128), 256, SMEMG>>>(
        g1h, g1l, gw2h, gw2l, gb2, nullptr, nullptr, gw3, gb3, BB, G1, G2);
    offsets_kernel<<<1, 32>>>();
    scatter_kernel<<<BB/256, 256>>>();

    // grouped expert layers: single-pass fp16, 4-stage
    const int T128 = NP/128 + NE;   // 264
    mma_gemm<true,true ,1,0,4><<<dim3(E1/128, T128), 256, SMEME>>>(
        obs_h, nullptr, ew1h, nullptr, eb1, h1, nullptr, nullptr, nullptr, 0, DOBS, E1);
    mma_gemm<true,false,1,0,4><<<dim3(E2/128, T128), 256, SMEME>>>(
        h1, nullptr, ew2h, nullptr, eb2, h2, nullptr, nullptr, nullptr, 0, E1, E2);
    mma_gemm<true,false,1,0,4><<<dim3(E3/128, T128), 256, SMEME>>>(
        h2, nullptr, ew3h, nullptr, eb3, h3, nullptr, nullptr, nullptr, 0, E2, E3);

    // layer 4 + weighted combine
    l4_combine_kernel<<<T128, 256>>>(ew4, eb4, out);
}

// round 16
// speedup vs baseline: 1.2642x; 1.0098x over previous
#include <cuda_runtime.h>
#include <cuda_fp16.h>
#include <cstdint>

#define BB   16384
#define DOBS 512
#define NE   8
#define NA   32
#define G1   256
#define G2   128
#define E1   1024
#define E2   512
#define E3   256
#define NP   (2*BB)

typedef __half h16;

// ---------------- scratch ----------------
__device__ __align__(16) h16 g_obs_h[BB*DOBS], g_obs_l[BB*DOBS];
__device__ __align__(16) h16 g_gw1h[DOBS*G1], g_gw1l[DOBS*G1];
__device__ __align__(16) h16 g_gw2h[G1*G2],   g_gw2l[G1*G2];
__device__ __align__(16) h16 g_ew1h[NE*DOBS*E1];
__device__ __align__(16) h16 g_ew2h[NE*E1*E2];
__device__ __align__(16) h16 g_ew3h[NE*E2*E3];

__device__ __align__(16) h16 g_g1h[BB*G1], g_g1l[BB*G1];
__device__ __align__(16) h16 g_h1[(size_t)NP*E1];
__device__ __align__(16) h16 g_h2[(size_t)NP*E2];
__device__ __align__(16) h16 g_h3[(size_t)NP*E3];

__device__ int   g_tidx[BB*2];
__device__ float g_tw[BB*2];
__device__ int   g_counts[NE];
__device__ int   g_cursor[NE];
__device__ int   g_tok[NP];
__device__ float g_wt[NP];

__device__ __forceinline__ float eluf(float x) { return x > 0.f ? x : expm1f(x); }

// prefix helper: given tile index bx (128-row tiles), find expert e, row0, rowEnd.
// returns false if bx beyond last tile or tile empty.
__device__ __forceinline__ bool tile_lookup(int bx, int& row0, int& rowEnd)
{
    int off = 0, tile = 0;
#pragma unroll
    for (int e = 0; e < NE; e++) {
        int c = g_counts[e];
        int t = (c + 127) >> 7;
        if (bx < tile + t) {
            row0   = off + (bx - tile) * 128;
            rowEnd = off + c;
            return row0 < rowEnd;
        }
        off += c; tile += t;
    }
    return false;
}

// ---------------- PTX helpers ----------------
__device__ __forceinline__ void mma_f16(float* c, const unsigned* a, const unsigned* b) {
    asm volatile(
        "mma.sync.aligned.m16n8k16.row.col.f32.f16.f16.f32 "
        "{%0,%1,%2,%3}, {%4,%5,%6,%7}, {%8,%9}, {%0,%1,%2,%3};"
        : "+f"(c[0]), "+f"(c[1]), "+f"(c[2]), "+f"(c[3])
        : "r"(a[0]), "r"(a[1]), "r"(a[2]), "r"(a[3]), "r"(b[0]), "r"(b[1]));
}
__device__ __forceinline__ void ldsm_x4(unsigned* r, unsigned addr) {
    asm volatile("ldmatrix.sync.aligned.m8n8.x4.shared.b16 {%0,%1,%2,%3}, [%4];"
                 : "=r"(r[0]), "=r"(r[1]), "=r"(r[2]), "=r"(r[3]) : "r"(addr));
}
__device__ __forceinline__ void ldsm_x4_t(unsigned* r, unsigned addr) {
    asm volatile("ldmatrix.sync.aligned.m8n8.x4.trans.shared.b16 {%0,%1,%2,%3}, [%4];"
                 : "=r"(r[0]), "=r"(r[1]), "=r"(r[2]), "=r"(r[3]) : "r"(addr));
}
__device__ __forceinline__ uint32_t s2u(const void* p) {
    uint32_t a;
    asm("{ .reg .u64 t; cvta.to.shared.u64 t, %1; cvt.u32.u64 %0, t; }" : "=r"(a) : "l"(p));
    return a;
}
__device__ __forceinline__ void cpa16(uint32_t dst, const void* src, uint32_t sz) {
    asm volatile("cp.async.cg.shared.global [%0], [%1], 16, %2;" :: "r"(dst), "l"(src), "r"(sz) : "memory");
}
__device__ __forceinline__ void cpcommit() { asm volatile("cp.async.commit_group;" ::: "memory"); }
template<int N> __device__ __forceinline__ void cpwait() { asm volatile("cp.async.wait_group %0;" :: "n"(N) : "memory"); }

// ---------------- fused split ----------------
struct SplitArgs {
    const float4* x[6];
    __half2*      hi[6];
    __half2*      lo[6];
    unsigned      end[6];
};

__global__ __launch_bounds__(256)
void split_all_kernel(SplitArgs a)
{
    if (blockIdx.x == 0 && threadIdx.x < NE) {
        g_counts[threadIdx.x] = 0;
        g_cursor[threadIdx.x] = 0;
    }
    unsigned i = blockIdx.x * 256 + threadIdx.x;
    if (i >= a.end[5]) return;
    int s = 0;
    while (i >= a.end[s]) s++;
    unsigned base = s ? a.end[s-1] : 0;
    unsigned j = i - base;
    float4 v = a.x[s][j];
    h16 h0 = __float2half_rn(v.x), h1 = __float2half_rn(v.y);
    h16 h2 = __float2half_rn(v.z), h3 = __float2half_rn(v.w);
    a.hi[s][2*j]   = __halves2half2(h0, h1);
    a.hi[s][2*j+1] = __halves2half2(h2, h3);
    if (a.lo[s]) {
        a.lo[s][2*j]   = __halves2half2(__float2half_rn(v.x - __half2float(h0)),
                                        __float2half_rn(v.y - __half2float(h1)));
        a.lo[s][2*j+1] = __halves2half2(__float2half_rn(v.z - __half2float(h2)),
                                        __float2half_rn(v.w - __half2float(h3)));
    }
}

// ---------------- pipelined fp16 TC grouped GEMM (128x128, BK=32, NSTG stages) ----------------
// Grid: x = n-tile (fast), y = row tile (grouped for experts, local prefix lookup).
// NPASS==3 (gating): C = Ah@Bh + Ah@Bl + Al@Bh  |  NPASS==1 (experts): C = A@Bh
// OUTM: 0 = fp16, 1 = fp16 hi/lo, 3 = fused topk (gate2)
#define A_BYTES 10240   // 128 x 40 halves
#define B_BYTES 8704    // 32 x 136 halves

template<bool GROUPED, bool GATHER, int NPASS, int OUTM, int NSTG>
__global__ __launch_bounds__(256)
void mma_gemm(const h16* __restrict__ Ah, const h16* __restrict__ Al,
              const h16* __restrict__ Wh, const h16* __restrict__ Wl,
              const float* __restrict__ bias,
              h16* __restrict__ Ch, h16* __restrict__ Cl,
              const float* __restrict__ gw3, const float* __restrict__ gb3,
              int M, int K, int N)
{
    constexpr bool TRI = (NPASS == 3);
    constexpr uint32_t AL_OFF = A_BYTES;
    constexpr uint32_t BH_OFF = TRI ? 2*A_BYTES : A_BYTES;
    constexpr uint32_t BL_OFF = BH_OFF + B_BYTES;
    constexpr uint32_t STG    = BH_OFF + (TRI ? 2 : 1) * B_BYTES;

    extern __shared__ __align__(128) char sm[];
    int row0, rowEnd;
    if (GROUPED) {
        // local prefix lookup + expert id
        int bx = blockIdx.y;
        int off = 0, tile = 0, e = 0;
        bool found = false;
#pragma unroll
        for (int ee = 0; ee < NE; ee++) {
            int c = g_counts[ee];
            int t = (c + 127) >> 7;
            if (!found && bx < tile + t) {
                row0   = off + (bx - tile) * 128;
                rowEnd = off + c;
                e = ee;
                found = true;
            }
            off += c; tile += t;
        }
        if (!found || row0 >= rowEnd) return;
        Wh   += (size_t)e * K * N;
        if (TRI) Wl += (size_t)e * K * N;
        bias += e * N;
    } else {
        row0   = blockIdx.y * 128;
        rowEnd = M;
    }
    const int n0  = blockIdx.x * 128;
    const int tid = threadIdx.x, lane = tid & 31, wid = tid >> 5;
    const int warpM = wid & 3, warpN = wid >> 2;
    const uint32_t su = s2u(sm);

    const int ar  = tid >> 2;
    const int ach = tid & 3;
    const h16 *pAh[2], *pAl[2];
    uint32_t asz[2];
#pragma unroll
    for (int i = 0; i < 2; i++) {
        int gr = row0 + ar + 64*i;
        bool v = gr < rowEnd;
        asz[i] = v ? 16u : 0u;
        size_t rowIdx = 0;
        if (v) rowIdx = GATHER ? (size_t)g_tok[gr] : (size_t)gr;
        pAh[i] = Ah + rowIdx * K + ach*8;
        if (TRI) pAl[i] = Al + rowIdx * K + ach*8;
    }
    const int br  = tid >> 4;
    const int bch = tid & 15;
    const h16* pBh = Wh + (size_t)br * N + n0 + bch*8;
    const h16* pBl = TRI ? (Wl + (size_t)br * N + n0 + bch*8) : nullptr;

    float acc[2][8][4];
#pragma unroll
    for (int mt = 0; mt < 2; mt++)
#pragma unroll
        for (int nt = 0; nt < 8; nt++)
#pragma unroll
            for (int q = 0; q < 4; q++) acc[mt][nt][q] = 0.f;

    const int S = K >> 5;

    auto LOAD = [&](int t) {
        uint32_t base = su + (uint32_t)(t % NSTG) * STG;
        int kf = t * 32;
#pragma unroll
        for (int i = 0; i < 2; i++) {
            uint32_t d = base + (uint32_t)((ar + 64*i)*80 + ach*16);
            cpa16(d, pAh[i] + kf, asz[i]);
            if (TRI) cpa16(d + AL_OFF, pAl[i] + kf, asz[i]);
        }
#pragma unroll
        for (int i = 0; i < 2; i++) {
            uint32_t d = base + (uint32_t)((br + 16*i)*272 + bch*16);
            cpa16(d + BH_OFF, pBh + (size_t)(kf + 16*i) * N, 16u);
            if (TRI) cpa16(d + BL_OFF, pBl + (size_t)(kf + 16*i) * N, 16u);
        }
        cpcommit();
    };

#pragma unroll
    for (int t = 0; t < NSTG-1; t++) LOAD(t);

    for (int s = 0; s < S; s++) {
        __syncthreads();
        int rem = S - 1 - s;
        if (rem >= NSTG-1) { LOAD(s + NSTG - 1); cpwait<NSTG-1>(); }
        else if (NSTG >= 4 && rem == 2) cpwait<(NSTG >= 4) ? 2 : 0>();
        else if (NSTG >= 3 && rem == 1) cpwait<(NSTG >= 3) ? 1 : 0>();
        else cpwait<0>();
        __syncthreads();

        const uint32_t aBase = su + (uint32_t)(s % NSTG) * STG;
#pragma unroll
        for (int kk = 0; kk < 32; kk += 16) {
            unsigned ah[2][4], al[2][4];
#pragma unroll
            for (int mt = 0; mt < 2; mt++) {
                uint32_t off = (uint32_t)(((warpM*32 + mt*16 + (lane & 15))*40 + kk + 8*(lane >> 4)) * 2);
                ldsm_x4(ah[mt], aBase + off);
                if (TRI) ldsm_x4(al[mt], aBase + AL_OFF + off);
            }
            const int brow = kk + (lane & 15);
#pragma unroll
            for (int np = 0; np < 4; np++) {
                const int bcol = warpN*64 + np*16 + 8*(lane >> 4);
                uint32_t boff = (uint32_t)((brow*136 + bcol) * 2);
                unsigned bh[4], bl[4];
                ldsm_x4_t(bh, aBase + BH_OFF + boff);
                if (TRI) ldsm_x4_t(bl, aBase + BL_OFF + boff);
#pragma unroll
                for (int mt = 0; mt < 2; mt++) {
                    mma_f16(acc[mt][2*np],   ah[mt], bh);
                    mma_f16(acc[mt][2*np+1], ah[mt], bh+2);
                    if (TRI) {
                        mma_f16(acc[mt][2*np],   ah[mt], bl);
                        mma_f16(acc[mt][2*np+1], ah[mt], bl+2);
                        mma_f16(acc[mt][2*np],   al[mt], bh);
                        mma_f16(acc[mt][2*np+1], al[mt], bh+2);
                    }
                }
            }
        }
    }

    // ---------------- epilogue ----------------
    if (OUTM == 3) {
        __syncthreads();
        float* sOut = (float*)sm;                    // 128*132*4 = 67584
        float* sW3  = (float*)(sm + 67584);          // 4096
        float* sB3  = (float*)(sm + 67584 + 4096);   // 32
#pragma unroll
        for (int mt = 0; mt < 2; mt++) {
            int rloc = warpM*32 + mt*16 + (lane >> 2);
#pragma unroll
            for (int nt = 0; nt < 8; nt++) {
                int c = warpN*64 + nt*8 + 2*(lane & 3);
                float b0 = __ldg(bias + c), b1 = __ldg(bias + c + 1);
                sOut[rloc*132 + c]         = eluf(acc[mt][nt][0] + b0);
                sOut[rloc*132 + c + 1]     = eluf(acc[mt][nt][1] + b1);
                sOut[(rloc+8)*132 + c]     = eluf(acc[mt][nt][2] + b0);
                sOut[(rloc+8)*132 + c + 1] = eluf(acc[mt][nt][3] + b1);
            }
        }
        for (int i = tid; i < G2*NE; i += 256) sW3[i] = gw3[i];
        if (tid < NE) sB3[tid] = gb3[tid];
        __syncthreads();

        if (tid < 128) {
            const int b = row0 + tid;
            float lg[NE];
#pragma unroll
            for (int j = 0; j < NE; j++) lg[j] = sB3[j];
#pragma unroll 4
            for (int k4 = 0; k4 < G2/4; k4++) {
                float4 v = *(const float4*)&sOut[tid*132 + k4*4];
                const float* w = sW3 + k4*4*NE;
#pragma unroll
                for (int j = 0; j < NE; j++)
                    lg[j] += v.x*w[j] + v.y*w[NE+j] + v.z*w[2*NE+j] + v.w*w[3*NE+j];
            }
            int i0 = 0; float m0 = lg[0];
#pragma unroll
            for (int j = 1; j < NE; j++) if (lg[j] > m0) { m0 = lg[j]; i0 = j; }
            int i1 = -1; float m1 = -3.4e38f;
#pragma unroll
            for (int j = 0; j < NE; j++) if (j != i0 && lg[j] > m1) { m1 = lg[j]; i1 = j; }
            float e1  = expf(m1 - m0);
            float inv = 1.f / (1.f + e1);
            g_tidx[b*2+0] = i0; g_tidx[b*2+1] = i1;
            g_tw[b*2+0] = inv;  g_tw[b*2+1] = e1 * inv;
            atomicAdd(&g_counts[i0], 1);
            atomicAdd(&g_counts[i1], 1);
        }
        return;
    }

#pragma unroll
    for (int mt = 0; mt < 2; mt++) {
        int r0 = row0 + warpM*32 + mt*16 + (lane >> 2);
#pragma unroll
        for (int nt = 0; nt < 8; nt++) {
            int c = n0 + warpN*64 + nt*8 + 2*(lane & 3);
            float b0 = __ldg(bias + c), b1 = __ldg(bias + c + 1);
            float v00 = eluf(acc[mt][nt][0] + b0);
            float v01 = eluf(acc[mt][nt][1] + b1);
            float v10 = eluf(acc[mt][nt][2] + b0);
            float v11 = eluf(acc[mt][nt][3] + b1);
#pragma unroll
            for (int rr = 0; rr < 2; rr++) {
                int r = r0 + rr*8;
                float va = rr ? v10 : v00, vb = rr ? v11 : v01;
                if (r < rowEnd) {
                    if (OUTM == 0) {
                        *(__half2*)(Ch + (size_t)r*N + c) =
                            __halves2half2(__float2half_rn(va), __float2half_rn(vb));
                    } else {
                        h16 h0 = __float2half_rn(va), h1 = __float2half_rn(vb);
                        *(__half2*)(Ch + (size_t)r*N + c) = __halves2half2(h0, h1);
                        *(__half2*)(Cl + (size_t)r*N + c) =
                            __halves2half2(__float2half_rn(va - __half2float(h0)),
                                           __float2half_rn(vb - __half2float(h1)));
                    }
                }
            }
        }
    }
}

// ---------------- scatter (computes offsets locally) ----------------
__global__ __launch_bounds__(256)
void scatter_kernel()
{
    // local prefix sums of g_counts (final after gate2)
    int off[NE];
    {
        int o = 0;
#pragma unroll
        for (int e = 0; e < NE; e++) { off[e] = o; o += g_counts[e]; }
    }
    const int b    = blockIdx.x * 256 + threadIdx.x;
    const int lane = threadIdx.x & 31;
#pragma unroll
    for (int s = 0; s < 2; s++) {
        int   e = g_tidx[b*2 + s];
        float w = g_tw[b*2 + s];
#pragma unroll
        for (int ee = 0; ee < NE; ee++) {
            unsigned m = __ballot_sync(0xffffffffu, e == ee);
            if (e == ee) {
                int rank   = __popc(m & ((1u << lane) - 1u));
                int leader = __ffs(m) - 1;
                int base = 0;
                if (lane == leader) base = atomicAdd(&g_cursor[ee], __popc(m));
                base = __shfl_sync(m, base, leader);
                int p = off[ee] + base + rank;
                g_tok[p] = b; g_wt[p] = w;
            }
        }
    }
}

// ---------------- layer 4 (K=256, N=32) + weighted combine, 128 rows/block ----------------
__global__ __launch_bounds__(256)
void l4_combine_kernel(const float* __restrict__ W4, const float* __restrict__ B4,
                       float* __restrict__ out)
{
    // local tile lookup (also need expert id)
    int bx = blockIdx.x;
    int row0 = 0, rowEnd = 0, e = 0;
    {
        int off = 0, tile = 0;
        bool found = false;
#pragma unroll
        for (int ee = 0; ee < NE; ee++) {
            int c = g_counts[ee];
            int t = (c + 127) >> 7;
            if (!found && bx < tile + t) {
                row0 = off + (bx - tile) * 128;
                rowEnd = off + c;
                e = ee;
                found = true;
            }
            off += c; tile += t;
        }
        if (!found || row0 >= rowEnd) return;
    }

    __shared__ float sW[E3*NA];
    const float* We = W4 + (size_t)e * E3 * NA;
    for (int i = threadIdx.x; i < E3*NA/4; i += 256)
        *(float4*)&sW[i*4] = *(const float4*)&We[i*4];
    __syncthreads();

    const int r  = threadIdx.x >> 3;
    const int c4 = (threadIdx.x & 7) * 4;
    const float bb0 = B4[e*NA + c4 + 0], bb1 = B4[e*NA + c4 + 1];
    const float bb2 = B4[e*NA + c4 + 2], bb3 = B4[e*NA + c4 + 3];

#pragma unroll
    for (int it = 0; it < 4; it++) {
        const int row = row0 + r + 32*it;
        if (row >= rowEnd) break;
        const __half2* hh = (const __half2*)(g_h3 + (size_t)row * E3);
        float a0 = 0.f, a1 = 0.f, a2 = 0.f, a3 = 0.f;
#pragma unroll 4
        for (int k = 0; k < E3; k += 4) {
            float2 p0 = __half22float2(hh[k/2]);
            float2 p1 = __half22float2(hh[k/2+1]);
            float4 w0 = *(float4*)&sW[(k+0)*NA + c4];
            float4 w1 = *(float4*)&sW[(k+1)*NA + c4];
            float4 w2 = *(float4*)&sW[(k+2)*NA + c4];
            float4 w3 = *(float4*)&sW[(k+3)*NA + c4];
            a0 += p0.x*w0.x + p0.y*w1.x + p1.x*w2.x + p1.y*w3.x;
            a1 += p0.x*w0.y + p0.y*w1.y + p1.x*w2.y + p1.y*w3.y;
            a2 += p0.x*w0.z + p0.y*w1.z + p1.x*w2.z + p1.y*w3.z;
            a3 += p0.x*w0.w + p0.y*w1.w + p1.x*w2.w + p1.y*w3.w;
        }
        const int   tok = g_tok[row];
        const float w   = g_wt[row];
        float* o = out + (size_t)tok * NA + c4;
        atomicAdd(o+0, w*(a0 + bb0));
        atomicAdd(o+1, w*(a1 + bb1));
        atomicAdd(o+2, w*(a2 + bb2));
        atomicAdd(o+3, w*(a3 + bb3));
    }
}

// ---------------- launch ----------------
#define SMEMG (2 * (2*A_BYTES + 2*B_BYTES))   // 75776 (gating, 2-stage)
#define SMEME (4 * (A_BYTES + B_BYTES))       // 75776 (experts, 4-stage)

extern "C" void kernel_launch(void* const* d_in, const int* in_sizes, int n_in,
                              void* d_out, int out_size)
{
    const float* obs = (const float*)d_in[0];
    const float* gw1 = (const float*)d_in[1];
    const float* gb1 = (const float*)d_in[2];
    const float* gw2 = (const float*)d_in[3];
    const float* gb2 = (const float*)d_in[4];
    const float* gw3 = (const float*)d_in[5];
    const float* gb3 = (const float*)d_in[6];
    const float* ew1 = (const float*)d_in[7];
    const float* eb1 = (const float*)d_in[8];
    const float* ew2 = (const float*)d_in[9];
    const float* eb2 = (const float*)d_in[10];
    const float* ew3 = (const float*)d_in[11];
    const float* eb3 = (const float*)d_in[12];
    const float* ew4 = (const float*)d_in[13];
    const float* eb4 = (const float*)d_in[14];
    float* out = (float*)d_out;

    h16 *obs_h, *obs_l, *gw1h, *gw1l, *gw2h, *gw2l;
    h16 *ew1h, *ew2h, *ew3h;
    h16 *g1h, *g1l, *h1, *h2, *h3;
    cudaGetSymbolAddress((void**)&obs_h, g_obs_h); cudaGetSymbolAddress((void**)&obs_l, g_obs_l);
    cudaGetSymbolAddress((void**)&gw1h, g_gw1h);   cudaGetSymbolAddress((void**)&gw1l, g_gw1l);
    cudaGetSymbolAddress((void**)&gw2h, g_gw2h);   cudaGetSymbolAddress((void**)&gw2l, g_gw2l);
    cudaGetSymbolAddress((void**)&ew1h, g_ew1h);
    cudaGetSymbolAddress((void**)&ew2h, g_ew2h);
    cudaGetSymbolAddress((void**)&ew3h, g_ew3h);
    cudaGetSymbolAddress((void**)&g1h, g_g1h);     cudaGetSymbolAddress((void**)&g1l, g_g1l);
    cudaGetSymbolAddress((void**)&h1, g_h1);
    cudaGetSymbolAddress((void**)&h2, g_h2);
    cudaGetSymbolAddress((void**)&h3, g_h3);

    cudaFuncSetAttribute(mma_gemm<false,false,3,1,2>, cudaFuncAttributeMaxDynamicSharedMemorySize, SMEMG);
    cudaFuncSetAttribute(mma_gemm<false,false,3,3,2>, cudaFuncAttributeMaxDynamicSharedMemorySize, SMEMG);
    cudaFuncSetAttribute(mma_gemm<true ,true ,1,0,4>, cudaFuncAttributeMaxDynamicSharedMemorySize, SMEME);
    cudaFuncSetAttribute(mma_gemm<true ,false,1,0,4>, cudaFuncAttributeMaxDynamicSharedMemorySize, SMEME);

    cudaMemsetAsync(out, 0, (size_t)out_size * sizeof(float));

    // fused splits (also zeroes counters)
    SplitArgs sa;
    unsigned n0 = BB*DOBS/4, n1 = DOBS*G1/4, n2 = G1*G2/4;
    unsigned n3 = NE*DOBS*E1/4, n4 = NE*E1*E2/4, n5 = NE*E2*E3/4;
    sa.x[0]=(const float4*)obs; sa.hi[0]=(__half2*)obs_h; sa.lo[0]=(__half2*)obs_l;
    sa.x[1]=(const float4*)gw1; sa.hi[1]=(__half2*)gw1h;  sa.lo[1]=(__half2*)gw1l;
    sa.x[2]=(const float4*)gw2; sa.hi[2]=(__half2*)gw2h;  sa.lo[2]=(__half2*)gw2l;
    sa.x[3]=(const float4*)ew1; sa.hi[3]=(__half2*)ew1h;  sa.lo[3]=nullptr;
    sa.x[4]=(const float4*)ew2; sa.hi[4]=(__half2*)ew2h;  sa.lo[4]=nullptr;
    sa.x[5]=(const float4*)ew3; sa.hi[5]=(__half2*)ew3h;  sa.lo[5]=nullptr;
    sa.end[0]=n0; sa.end[1]=n0+n1; sa.end[2]=n0+n1+n2;
    sa.end[3]=sa.end[2]+n3; sa.end[4]=sa.end[3]+n4; sa.end[5]=sa.end[4]+n5;
    split_all_kernel<<<(sa.end[5] + 255)/256, 256>>>(sa);

    // gating MLP: 3-pass exact, 2-stage; gate2 fuses logits+top2+counts
    mma_gemm<false,false,3,1,2><<<dim3(G1/128, BB/128), 256, SMEMG>>>(
        obs_h, obs_l, gw1h, gw1l, gb1, g1h, g1l, nullptr, nullptr, BB, DOBS, G1);
    mma_gemm<false,false,3,3,2><<<dim3(G2/128, BB/128), 256, SMEMG>>>(
        g1h, g1l, gw2h, gw2l, gb2, nullptr, nullptr, gw3, gb3, BB, G1, G2);
    scatter_kernel<<<BB/256, 256>>>();

    // grouped expert layers: single-pass fp16, 4-stage (local prefix lookup)
    const int T128 = NP/128 + NE;   // 264
    mma_gemm<true,true ,1,0,4><<<dim3(E1/128, T128), 256, SMEME>>>(
        obs_h, nullptr, ew1h, nullptr, eb1, h1, nullptr, nullptr, nullptr, 0, DOBS, E1);
    mma_gemm<true,false,1,0,4><<<dim3(E2/128, T128), 256, SMEME>>>(
        h1, nullptr, ew2h, nullptr, eb2, h2, nullptr, nullptr, nullptr, 0, E1, E2);
    mma_gemm<true,false,1,0,4><<<dim3(E3/128, T128), 256, SMEME>>>(
        h2, nullptr, ew3h, nullptr, eb3, h3, nullptr, nullptr, nullptr, 0, E2, E3);

    // layer 4 + weighted combine
    l4_combine_kernel<<<T128, 256>>>(ew4, eb4, out);
}

// round 17
// speedup vs baseline: 1.2862x; 1.0174x over previous
#include <cuda_runtime.h>
#include <cuda_fp16.h>
#include <cstdint>

#define BB   16384
#define DOBS 512
#define NE   8
#define NA   32
#define G1   256
#define G2   128
#define E1   1024
#define E2   512
#define E3   256
#define NP   (2*BB)

typedef __half h16;

// ---------------- scratch ----------------
__device__ __align__(16) h16 g_obs_h[BB*DOBS], g_obs_l[BB*DOBS];
__device__ __align__(16) h16 g_gw1h[DOBS*G1], g_gw1l[DOBS*G1];
__device__ __align__(16) h16 g_gw2h[G1*G2],   g_gw2l[G1*G2];
__device__ __align__(16) h16 g_ew1h[NE*DOBS*E1];
__device__ __align__(16) h16 g_ew2h[NE*E1*E2];
__device__ __align__(16) h16 g_ew3h[NE*E2*E3];

__device__ __align__(16) h16 g_g1h[BB*G1], g_g1l[BB*G1];
__device__ __align__(16) h16 g_h1[(size_t)NP*E1];
__device__ __align__(16) h16 g_h2[(size_t)NP*E2];
__device__ __align__(16) h16 g_h3[(size_t)NP*E3];

__device__ int   g_tidx[BB*2];
__device__ float g_tw[BB*2];
__device__ int   g_counts[NE];
__device__ int   g_cursor[NE];
__device__ int   g_tok[NP];
__device__ float g_wt[NP];

__device__ __forceinline__ float eluf(float x) { return x > 0.f ? x : expm1f(x); }

// ---------------- PTX helpers ----------------
__device__ __forceinline__ void mma_f16(float* c, const unsigned* a, const unsigned* b) {
    asm volatile(
        "mma.sync.aligned.m16n8k16.row.col.f32.f16.f16.f32 "
        "{%0,%1,%2,%3}, {%4,%5,%6,%7}, {%8,%9}, {%0,%1,%2,%3};"
        : "+f"(c[0]), "+f"(c[1]), "+f"(c[2]), "+f"(c[3])
        : "r"(a[0]), "r"(a[1]), "r"(a[2]), "r"(a[3]), "r"(b[0]), "r"(b[1]));
}
__device__ __forceinline__ void ldsm_x4(unsigned* r, unsigned addr) {
    asm volatile("ldmatrix.sync.aligned.m8n8.x4.shared.b16 {%0,%1,%2,%3}, [%4];"
                 : "=r"(r[0]), "=r"(r[1]), "=r"(r[2]), "=r"(r[3]) : "r"(addr));
}
__device__ __forceinline__ void ldsm_x4_t(unsigned* r, unsigned addr) {
    asm volatile("ldmatrix.sync.aligned.m8n8.x4.trans.shared.b16 {%0,%1,%2,%3}, [%4];"
                 : "=r"(r[0]), "=r"(r[1]), "=r"(r[2]), "=r"(r[3]) : "r"(addr));
}
__device__ __forceinline__ uint32_t s2u(const void* p) {
    uint32_t a;
    asm("{ .reg .u64 t; cvta.to.shared.u64 t, %1; cvt.u32.u64 %0, t; }" : "=r"(a) : "l"(p));
    return a;
}
__device__ __forceinline__ void cpa16(uint32_t dst, const void* src, uint32_t sz) {
    asm volatile("cp.async.cg.shared.global [%0], [%1], 16, %2;" :: "r"(dst), "l"(src), "r"(sz) : "memory");
}
__device__ __forceinline__ void cpcommit() { asm volatile("cp.async.commit_group;" ::: "memory"); }
template<int N> __device__ __forceinline__ void cpwait() { asm volatile("cp.async.wait_group %0;" :: "n"(N) : "memory"); }

// ---------------- fused split ----------------
struct SplitArgs {
    const float4* x[6];
    __half2*      hi[6];
    __half2*      lo[6];
    unsigned      end[6];
};

__global__ __launch_bounds__(256)
void split_all_kernel(SplitArgs a)
{
    if (blockIdx.x == 0 && threadIdx.x < NE) {
        g_counts[threadIdx.x] = 0;
        g_cursor[threadIdx.x] = 0;
    }
    unsigned i = blockIdx.x * 256 + threadIdx.x;
    if (i >= a.end[5]) return;
    int s = 0;
    while (i >= a.end[s]) s++;
    unsigned base = s ? a.end[s-1] : 0;
    unsigned j = i - base;
    float4 v = a.x[s][j];
    h16 h0 = __float2half_rn(v.x), h1 = __float2half_rn(v.y);
    h16 h2 = __float2half_rn(v.z), h3 = __float2half_rn(v.w);
    a.hi[s][2*j]   = __halves2half2(h0, h1);
    a.hi[s][2*j+1] = __halves2half2(h2, h3);
    if (a.lo[s]) {
        a.lo[s][2*j]   = __halves2half2(__float2half_rn(v.x - __half2float(h0)),
                                        __float2half_rn(v.y - __half2float(h1)));
        a.lo[s][2*j+1] = __halves2half2(__float2half_rn(v.z - __half2float(h2)),
                                        __float2half_rn(v.w - __half2float(h3)));
    }
}

// ---------------- pipelined fp16 TC grouped GEMM (128x128, BK=32, NSTG stages) ----------------
// Grid: x = n-tile (fast), y = row tile (grouped for experts, local prefix lookup).
// NPASS==3 (gating): C = Ah@Bh + Ah@Bl + Al@Bh  |  NPASS==1 (experts): C = A@Bh
// OUTM: 0 = fp16, 1 = fp16 hi/lo, 3 = fused topk (gate2)
#define A_BYTES 10240   // 128 x 40 halves
#define B_BYTES 8704    // 32 x 136 halves

template<bool GROUPED, bool GATHER, int NPASS, int OUTM, int NSTG>
__global__ __launch_bounds__(256)
void mma_gemm(const h16* __restrict__ Ah, const h16* __restrict__ Al,
              const h16* __restrict__ Wh, const h16* __restrict__ Wl,
              const float* __restrict__ bias,
              h16* __restrict__ Ch, h16* __restrict__ Cl,
              const float* __restrict__ gw3, const float* __restrict__ gb3,
              int M, int K, int N)
{
    constexpr bool TRI = (NPASS == 3);
    constexpr uint32_t AL_OFF = A_BYTES;
    constexpr uint32_t BH_OFF = TRI ? 2*A_BYTES : A_BYTES;
    constexpr uint32_t BL_OFF = BH_OFF + B_BYTES;
    constexpr uint32_t STG    = BH_OFF + (TRI ? 2 : 1) * B_BYTES;

    extern __shared__ __align__(128) char sm[];
    int row0, rowEnd;
    if (GROUPED) {
        int bx = blockIdx.y;
        int off = 0, tile = 0, e = 0;
        bool found = false;
#pragma unroll
        for (int ee = 0; ee < NE; ee++) {
            int c = g_counts[ee];
            int t = (c + 127) >> 7;
            if (!found && bx < tile + t) {
                row0   = off + (bx - tile) * 128;
                rowEnd = off + c;
                e = ee;
                found = true;
            }
            off += c; tile += t;
        }
        if (!found || row0 >= rowEnd) return;
        Wh   += (size_t)e * K * N;
        if (TRI) Wl += (size_t)e * K * N;
        bias += e * N;
    } else {
        row0   = blockIdx.y * 128;
        rowEnd = M;
    }
    const int n0  = blockIdx.x * 128;
    const int tid = threadIdx.x, lane = tid & 31, wid = tid >> 5;
    const int warpM = wid & 3, warpN = wid >> 2;
    const uint32_t su = s2u(sm);

    const int ar  = tid >> 2;
    const int ach = tid & 3;
    const h16 *pAh[2], *pAl[2];
    uint32_t asz[2];
#pragma unroll
    for (int i = 0; i < 2; i++) {
        int gr = row0 + ar + 64*i;
        bool v = gr < rowEnd;
        asz[i] = v ? 16u : 0u;
        size_t rowIdx = 0;
        if (v) rowIdx = GATHER ? (size_t)g_tok[gr] : (size_t)gr;
        pAh[i] = Ah + rowIdx * K + ach*8;
        if (TRI) pAl[i] = Al + rowIdx * K + ach*8;
    }
    const int br  = tid >> 4;
    const int bch = tid & 15;
    const h16* pBh = Wh + (size_t)br * N + n0 + bch*8;
    const h16* pBl = TRI ? (Wl + (size_t)br * N + n0 + bch*8) : nullptr;

    float acc[2][8][4];
#pragma unroll
    for (int mt = 0; mt < 2; mt++)
#pragma unroll
        for (int nt = 0; nt < 8; nt++)
#pragma unroll
            for (int q = 0; q < 4; q++) acc[mt][nt][q] = 0.f;

    const int S = K >> 5;

    auto LOAD = [&](int t) {
        uint32_t base = su + (uint32_t)(t % NSTG) * STG;
        int kf = t * 32;
#pragma unroll
        for (int i = 0; i < 2; i++) {
            uint32_t d = base + (uint32_t)((ar + 64*i)*80 + ach*16);
            cpa16(d, pAh[i] + kf, asz[i]);
            if (TRI) cpa16(d + AL_OFF, pAl[i] + kf, asz[i]);
        }
#pragma unroll
        for (int i = 0; i < 2; i++) {
            uint32_t d = base + (uint32_t)((br + 16*i)*272 + bch*16);
            cpa16(d + BH_OFF, pBh + (size_t)(kf + 16*i) * N, 16u);
            if (TRI) cpa16(d + BL_OFF, pBl + (size_t)(kf + 16*i) * N, 16u);
        }
        cpcommit();
    };

#pragma unroll
    for (int t = 0; t < NSTG-1; t++) LOAD(t);

    for (int s = 0; s < S; s++) {
        __syncthreads();
        int rem = S - 1 - s;
        if (rem >= NSTG-1) { LOAD(s + NSTG - 1); cpwait<NSTG-1>(); }
        else if (NSTG >= 4 && rem == 2) cpwait<(NSTG >= 4) ? 2 : 0>();
        else if (NSTG >= 3 && rem == 1) cpwait<(NSTG >= 3) ? 1 : 0>();
        else cpwait<0>();
        __syncthreads();

        const uint32_t aBase = su + (uint32_t)(s % NSTG) * STG;
#pragma unroll
        for (int kk = 0; kk < 32; kk += 16) {
            unsigned ah[2][4], al[2][4];
#pragma unroll
            for (int mt = 0; mt < 2; mt++) {
                uint32_t off = (uint32_t)(((warpM*32 + mt*16 + (lane & 15))*40 + kk + 8*(lane >> 4)) * 2);
                ldsm_x4(ah[mt], aBase + off);
                if (TRI) ldsm_x4(al[mt], aBase + AL_OFF + off);
            }
            const int brow = kk + (lane & 15);
#pragma unroll
            for (int np = 0; np < 4; np++) {
                const int bcol = warpN*64 + np*16 + 8*(lane >> 4);
                uint32_t boff = (uint32_t)((brow*136 + bcol) * 2);
                unsigned bh[4], bl[4];
                ldsm_x4_t(bh, aBase + BH_OFF + boff);
                if (TRI) ldsm_x4_t(bl, aBase + BL_OFF + boff);
#pragma unroll
                for (int mt = 0; mt < 2; mt++) {
                    mma_f16(acc[mt][2*np],   ah[mt], bh);
                    mma_f16(acc[mt][2*np+1], ah[mt], bh+2);
                    if (TRI) {
                        mma_f16(acc[mt][2*np],   ah[mt], bl);
                        mma_f16(acc[mt][2*np+1], ah[mt], bl+2);
                        mma_f16(acc[mt][2*np],   al[mt], bh);
                        mma_f16(acc[mt][2*np+1], al[mt], bh+2);
                    }
                }
            }
        }
    }

    // ---------------- epilogue ----------------
    if (OUTM == 3) {
        __syncthreads();
        float* sOut = (float*)sm;                    // 128*132*4 = 67584
        float* sW3  = (float*)(sm + 67584);          // 4096
        float* sB3  = (float*)(sm + 67584 + 4096);   // 32
#pragma unroll
        for (int mt = 0; mt < 2; mt++) {
            int rloc = warpM*32 + mt*16 + (lane >> 2);
#pragma unroll
            for (int nt = 0; nt < 8; nt++) {
                int c = warpN*64 + nt*8 + 2*(lane & 3);
                float b0 = __ldg(bias + c), b1 = __ldg(bias + c + 1);
                sOut[rloc*132 + c]         = eluf(acc[mt][nt][0] + b0);
                sOut[rloc*132 + c + 1]     = eluf(acc[mt][nt][1] + b1);
                sOut[(rloc+8)*132 + c]     = eluf(acc[mt][nt][2] + b0);
                sOut[(rloc+8)*132 + c + 1] = eluf(acc[mt][nt][3] + b1);
            }
        }
        for (int i = tid; i < G2*NE; i += 256) sW3[i] = gw3[i];
        if (tid < NE) sB3[tid] = gb3[tid];
        __syncthreads();

        if (tid < 128) {
            const int b = row0 + tid;
            float lg[NE];
#pragma unroll
            for (int j = 0; j < NE; j++) lg[j] = sB3[j];
#pragma unroll 4
            for (int k4 = 0; k4 < G2/4; k4++) {
                float4 v = *(const float4*)&sOut[tid*132 + k4*4];
                const float* w = sW3 + k4*4*NE;
#pragma unroll
                for (int j = 0; j < NE; j++)
                    lg[j] += v.x*w[j] + v.y*w[NE+j] + v.z*w[2*NE+j] + v.w*w[3*NE+j];
            }
            int i0 = 0; float m0 = lg[0];
#pragma unroll
            for (int j = 1; j < NE; j++) if (lg[j] > m0) { m0 = lg[j]; i0 = j; }
            int i1 = -1; float m1 = -3.4e38f;
#pragma unroll
            for (int j = 0; j < NE; j++) if (j != i0 && lg[j] > m1) { m1 = lg[j]; i1 = j; }
            float e1  = expf(m1 - m0);
            float inv = 1.f / (1.f + e1);
            g_tidx[b*2+0] = i0; g_tidx[b*2+1] = i1;
            g_tw[b*2+0] = inv;  g_tw[b*2+1] = e1 * inv;
            atomicAdd(&g_counts[i0], 1);
            atomicAdd(&g_counts[i1], 1);
        }
        return;
    }

#pragma unroll
    for (int mt = 0; mt < 2; mt++) {
        int r0 = row0 + warpM*32 + mt*16 + (lane >> 2);
#pragma unroll
        for (int nt = 0; nt < 8; nt++) {
            int c = n0 + warpN*64 + nt*8 + 2*(lane & 3);
            float b0 = __ldg(bias + c), b1 = __ldg(bias + c + 1);
            float v00 = eluf(acc[mt][nt][0] + b0);
            float v01 = eluf(acc[mt][nt][1] + b1);
            float v10 = eluf(acc[mt][nt][2] + b0);
            float v11 = eluf(acc[mt][nt][3] + b1);
#pragma unroll
            for (int rr = 0; rr < 2; rr++) {
                int r = r0 + rr*8;
                float va = rr ? v10 : v00, vb = rr ? v11 : v01;
                if (r < rowEnd) {
                    if (OUTM == 0) {
                        *(__half2*)(Ch + (size_t)r*N + c) =
                            __halves2half2(__float2half_rn(va), __float2half_rn(vb));
                    } else {
                        h16 h0 = __float2half_rn(va), h1 = __float2half_rn(vb);
                        *(__half2*)(Ch + (size_t)r*N + c) = __halves2half2(h0, h1);
                        *(__half2*)(Cl + (size_t)r*N + c) =
                            __halves2half2(__float2half_rn(va - __half2float(h0)),
                                           __float2half_rn(vb - __half2float(h1)));
                    }
                }
            }
        }
    }
}

// ---------------- scatter: smem-aggregated ranks, 8 global atomics per block ----------------
__global__ __launch_bounds__(256)
void scatter_kernel()
{
    __shared__ int sCnt[2][NE];
    __shared__ int sBase[2][NE];

    // local prefix sums of g_counts (final after gate2)
    int off[NE];
    {
        int o = 0;
#pragma unroll
        for (int e = 0; e < NE; e++) { off[e] = o; o += g_counts[e]; }
    }
    const int tid = threadIdx.x;
    const int b   = blockIdx.x * 256 + tid;
    if (tid < 2*NE) ((int*)sCnt)[tid] = 0;
    const int   e0 = g_tidx[b*2+0], e1 = g_tidx[b*2+1];
    const float w0 = g_tw[b*2+0],   w1 = g_tw[b*2+1];
    __syncthreads();
    int r0 = atomicAdd(&sCnt[0][e0], 1);
    int r1 = atomicAdd(&sCnt[1][e1], 1);
    __syncthreads();
    if (tid < NE) {
        int c0 = sCnt[0][tid], c1 = sCnt[1][tid];
        int base = atomicAdd(&g_cursor[tid], c0 + c1);
        sBase[0][tid] = base;
        sBase[1][tid] = base + c0;
    }
    __syncthreads();
    int p0 = off[e0] + sBase[0][e0] + r0;
    g_tok[p0] = b; g_wt[p0] = w0;
    int p1 = off[e1] + sBase[1][e1] + r1;
    g_tok[p1] = b; g_wt[p1] = w1;
}

// ---------------- layer 4 (K=256, N=32) + weighted combine, 128 rows/block ----------------
__global__ __launch_bounds__(256)
void l4_combine_kernel(const float* __restrict__ W4, const float* __restrict__ B4,
                       float* __restrict__ out)
{
    int bx = blockIdx.x;
    int row0 = 0, rowEnd = 0, e = 0;
    {
        int off = 0, tile = 0;
        bool found = false;
#pragma unroll
        for (int ee = 0; ee < NE; ee++) {
            int c = g_counts[ee];
            int t = (c + 127) >> 7;
            if (!found && bx < tile + t) {
                row0 = off + (bx - tile) * 128;
                rowEnd = off + c;
                e = ee;
                found = true;
            }
            off += c; tile += t;
        }
        if (!found || row0 >= rowEnd) return;
    }

    __shared__ float sW[E3*NA];
    const float* We = W4 + (size_t)e * E3 * NA;
    for (int i = threadIdx.x; i < E3*NA/4; i += 256)
        *(float4*)&sW[i*4] = *(const float4*)&We[i*4];
    __syncthreads();

    const int r  = threadIdx.x >> 3;
    const int c4 = (threadIdx.x & 7) * 4;
    const float bb0 = B4[e*NA + c4 + 0], bb1 = B4[e*NA + c4 + 1];
    const float bb2 = B4[e*NA + c4 + 2], bb3 = B4[e*NA + c4 + 3];

#pragma unroll
    for (int it = 0; it < 4; it++) {
        const int row = row0 + r + 32*it;
        if (row >= rowEnd) break;
        const __half2* hh = (const __half2*)(g_h3 + (size_t)row * E3);
        float a0 = 0.f, a1 = 0.f, a2 = 0.f, a3 = 0.f;
#pragma unroll 4
        for (int k = 0; k < E3; k += 4) {
            float2 p0 = __half22float2(hh[k/2]);
            float2 p1 = __half22float2(hh[k/2+1]);
            float4 w0 = *(float4*)&sW[(k+0)*NA + c4];
            float4 w1 = *(float4*)&sW[(k+1)*NA + c4];
            float4 w2 = *(float4*)&sW[(k+2)*NA + c4];
            float4 w3 = *(float4*)&sW[(k+3)*NA + c4];
            a0 += p0.x*w0.x + p0.y*w1.x + p1.x*w2.x + p1.y*w3.x;
            a1 += p0.x*w0.y + p0.y*w1.y + p1.x*w2.y + p1.y*w3.y;
            a2 += p0.x*w0.z + p0.y*w1.z + p1.x*w2.z + p1.y*w3.z;
            a3 += p0.x*w0.w + p0.y*w1.w + p1.x*w2.w + p1.y*w3.w;
        }
        const int   tok = g_tok[row];
        const float w   = g_wt[row];
        float* o = out + (size_t)tok * NA + c4;
        atomicAdd(o+0, w*(a0 + bb0));
        atomicAdd(o+1, w*(a1 + bb1));
        atomicAdd(o+2, w*(a2 + bb2));
        atomicAdd(o+3, w*(a3 + bb3));
    }
}

// ---------------- launch ----------------
#define SMEMG (2 * (2*A_BYTES + 2*B_BYTES))   // 75776 (gating, 2-stage)
#define SMEME (4 * (A_BYTES + B_BYTES))       // 75776 (experts, 4-stage)

extern "C" void kernel_launch(void* const* d_in, const int* in_sizes, int n_in,
                              void* d_out, int out_size)
{
    const float* obs = (const float*)d_in[0];
    const float* gw1 = (const float*)d_in[1];
    const float* gb1 = (const float*)d_in[2];
    const float* gw2 = (const float*)d_in[3];
    const float* gb2 = (const float*)d_in[4];
    const float* gw3 = (const float*)d_in[5];
    const float* gb3 = (const float*)d_in[6];
    const float* ew1 = (const float*)d_in[7];
    const float* eb1 = (const float*)d_in[8];
    const float* ew2 = (const float*)d_in[9];
    const float* eb2 = (const float*)d_in[10];
    const float* ew3 = (const float*)d_in[11];
    const float* eb3 = (const float*)d_in[12];
    const float* ew4 = (const float*)d_in[13];
    const float* eb4 = (const float*)d_in[14];
    float* out = (float*)d_out;

    h16 *obs_h, *obs_l, *gw1h, *gw1l, *gw2h, *gw2l;
    h16 *ew1h, *ew2h, *ew3h;
    h16 *g1h, *g1l, *h1, *h2, *h3;
    cudaGetSymbolAddress((void**)&obs_h, g_obs_h); cudaGetSymbolAddress((void**)&obs_l, g_obs_l);
    cudaGetSymbolAddress((void**)&gw1h, g_gw1h);   cudaGetSymbolAddress((void**)&gw1l, g_gw1l);
    cudaGetSymbolAddress((void**)&gw2h, g_gw2h);   cudaGetSymbolAddress((void**)&gw2l, g_gw2l);
    cudaGetSymbolAddress((void**)&ew1h, g_ew1h);
    cudaGetSymbolAddress((void**)&ew2h, g_ew2h);
    cudaGetSymbolAddress((void**)&ew3h, g_ew3h);
    cudaGetSymbolAddress((void**)&g1h, g_g1h);     cudaGetSymbolAddress((void**)&g1l, g_g1l);
    cudaGetSymbolAddress((void**)&h1, g_h1);
    cudaGetSymbolAddress((void**)&h2, g_h2);
    cudaGetSymbolAddress((void**)&h3, g_h3);

    cudaFuncSetAttribute(mma_gemm<false,false,3,1,2>, cudaFuncAttributeMaxDynamicSharedMemorySize, SMEMG);
    cudaFuncSetAttribute(mma_gemm<false,false,3,3,2>, cudaFuncAttributeMaxDynamicSharedMemorySize, SMEMG);
    cudaFuncSetAttribute(mma_gemm<true ,true ,1,0,4>, cudaFuncAttributeMaxDynamicSharedMemorySize, SMEME);
    cudaFuncSetAttribute(mma_gemm<true ,false,1,0,4>, cudaFuncAttributeMaxDynamicSharedMemorySize, SMEME);

    cudaMemsetAsync(out, 0, (size_t)out_size * sizeof(float));

    // fused splits (also zeroes counters)
    SplitArgs sa;
    unsigned n0 = BB*DOBS/4, n1 = DOBS*G1/4, n2 = G1*G2/4;
    unsigned n3 = NE*DOBS*E1/4, n4 = NE*E1*E2/4, n5 = NE*E2*E3/4;
    sa.x[0]=(const float4*)obs; sa.hi[0]=(__half2*)obs_h; sa.lo[0]=(__half2*)obs_l;
    sa.x[1]=(const float4*)gw1; sa.hi[1]=(__half2*)gw1h;  sa.lo[1]=(__half2*)gw1l;
    sa.x[2]=(const float4*)gw2; sa.hi[2]=(__half2*)gw2h;  sa.lo[2]=(__half2*)gw2l;
    sa.x[3]=(const float4*)ew1; sa.hi[3]=(__half2*)ew1h;  sa.lo[3]=nullptr;
    sa.x[4]=(const float4*)ew2; sa.hi[4]=(__half2*)ew2h;  sa.lo[4]=nullptr;
    sa.x[5]=(const float4*)ew3; sa.hi[5]=(__half2*)ew3h;  sa.lo[5]=nullptr;
    sa.end[0]=n0; sa.end[1]=n0+n1; sa.end[2]=n0+n1+n2;
    sa.end[3]=sa.end[2]+n3; sa.end[4]=sa.end[3]+n4; sa.end[5]=sa.end[4]+n5;
    split_all_kernel<<<(sa.end[5] + 255)/256, 256>>>(sa);

    // gating MLP: 3-pass exact, 2-stage; gate2 fuses logits+top2+counts
    mma_gemm<false,false,3,1,2><<<dim3(G1/128, BB/128), 256, SMEMG>>>(
        obs_h, obs_l, gw1h, gw1l, gb1, g1h, g1l, nullptr, nullptr, BB, DOBS, G1);
    mma_gemm<false,false,3,3,2><<<dim3(G2/128, BB/128), 256, SMEMG>>>(
        g1h, g1l, gw2h, gw2l, gb2, nullptr, nullptr, gw3, gb3, BB, G1, G2);
    scatter_kernel<<<BB/256, 256>>>();

    // grouped expert layers: single-pass fp16, 4-stage (local prefix lookup)
    const int T128 = NP/128 + NE;   // 264
    mma_gemm<true,true ,1,0,4><<<dim3(E1/128, T128), 256, SMEME>>>(
        obs_h, nullptr, ew1h, nullptr, eb1, h1, nullptr, nullptr, nullptr, 0, DOBS, E1);
    mma_gemm<true,false,1,0,4><<<dim3(E2/128, T128), 256, SMEME>>>(
        h1, nullptr, ew2h, nullptr, eb2, h2, nullptr, nullptr, nullptr, 0, E1, E2);
    mma_gemm<true,false,1,0,4><<<dim3(E3/128, T128), 256, SMEME>>>(
        h2, nullptr, ew3h, nullptr, eb3, h3, nullptr, nullptr, nullptr, 0, E2, E3);

    // layer 4 + weighted combine
    l4_combine_kernel<<<T128, 256>>>(ew4, eb4, out);
}